// round 14
// baseline (speedup 1.0000x reference)
#include <cuda_runtime.h>
#include <cuda_bf16.h>
#include <cuda_fp16.h>
#include <cstdint>

// ---------------------------------------------------------------------------
// GAT (4 layers) + pairwise tanh for GB300 (sm_103a harness, compute_103 PTX).
// GEMM: fp16 HMMA, A single fp16, W fp16 hi/lo split (C = A*Wh + A*Wl).
// block 64x128, 128 thr, 4 warps 32x64, ldmatrix.x4 + reg fragment prefetch,
// 3-stage cp.async pipeline, fused attention-dot epilogue, fp16 f.
// Aggregation: 1 warp/node (R12 structure), prefetch depth 2.
// CSR: node-major histogram + warp scans.
// ---------------------------------------------------------------------------

constexpr int HD  = 384;        // H*D
constexpr int NH  = 6;          // heads
constexpr int NMAXI = 5120;     // max nodes (actual 5000), mult of 128
constexpr int EMAXI = 163840;
constexpr int CSZ   = 320;      // edges per sort chunk
constexpr int NCHP  = 512;      // chunk stride (chunks actual 500)

// ------------------------- device scratch ----------------------------------
__device__ __align__(16) __half g_f16[NMAXI * HD];           // fp16 GEMM out
__device__ __align__(16) __half g_A16[NMAXI * HD];           // fp16 layer input
__device__ __align__(16) __half g_Wh4[4 * HD * HD];          // W^T hi [l][n][k]
__device__ __align__(16) __half g_Wl4[4 * HD * HD];          // W^T lo
__device__ float g_el[NMAXI * NH];
__device__ float g_er[NMAXI * NH];
__device__ __align__(16) int g_histT[NMAXI * NCHP];          // node-major counts
__device__ int   g_base[NMAXI];
__device__ int   g_deg[NMAXI];
__device__ int   g_csr[EMAXI];
__device__ __align__(16) float g_s1[NMAXI];
__device__ __align__(16) float g_s2[NMAXI];

// --------------------------- helpers ----------------------------------------
__device__ __forceinline__ uint32_t smem_u32(const void* p) {
    uint32_t a;
    asm("{ .reg .u64 t; cvta.to.shared.u64 t, %1; cvt.u32.u64 %0, t; }"
        : "=r"(a) : "l"(p));
    return a;
}
__device__ __forceinline__ void cpa16(uint32_t s, const void* g) {
    asm volatile("cp.async.ca.shared.global [%0], [%1], 16;"
                 :: "r"(s), "l"(g) : "memory");
}
__device__ __forceinline__ void cpa_commit() {
    asm volatile("cp.async.commit_group;" ::: "memory");
}
__device__ __forceinline__ void cpa_wait0() {
    asm volatile("cp.async.wait_group 0;" ::: "memory");
}
__device__ __forceinline__ void cpa_wait1() {
    asm volatile("cp.async.wait_group 1;" ::: "memory");
}
__device__ __forceinline__ void mma_f16(float* d, const uint32_t* a,
                                        const uint32_t* b) {
    asm volatile(
        "mma.sync.aligned.m16n8k16.row.col.f32.f16.f16.f32 "
        "{%0,%1,%2,%3}, {%4,%5,%6,%7}, {%8,%9}, {%0,%1,%2,%3};"
        : "+f"(d[0]), "+f"(d[1]), "+f"(d[2]), "+f"(d[3])
        : "r"(a[0]), "r"(a[1]), "r"(a[2]), "r"(a[3]), "r"(b[0]), "r"(b[1]));
}
__device__ __forceinline__ void ldsm_x4(uint32_t& r0, uint32_t& r1,
                                        uint32_t& r2, uint32_t& r3,
                                        uint32_t addr) {
    asm volatile("ldmatrix.sync.aligned.m8n8.x4.shared.b16 {%0,%1,%2,%3}, [%4];"
                 : "=r"(r0), "=r"(r1), "=r"(r2), "=r"(r3) : "r"(addr));
}
__device__ __forceinline__ uint32_t pack_h2(float a, float b) {
    __half2 h = __floats2half2_rn(a, b);
    return *reinterpret_cast<uint32_t*>(&h);
}

// -------------- conversions + histogram zero (one kernel, runs first) -------
__global__ void k_convAB(const float* __restrict__ nfeats,
                         const float* __restrict__ w0, const float* __restrict__ w1,
                         const float* __restrict__ w2, const float* __restrict__ w3,
                         int M, int Mpad) {
    int idx = blockIdx.x * blockDim.x + threadIdx.x;
    int asz = Mpad * HD;
    int bsz = 4 * HD * HD;
    if (idx < asz) {
        int m = idx / HD, k = idx - m * HD;
        float v = (m < M && k < 131) ? nfeats[(size_t)m * 131 + k] : 0.f;
        g_A16[idx] = __float2half_rn(v);
    } else if (idx < asz + bsz) {
        int r = idx - asz;
        int lb = r / (HD * HD);
        int q = r - lb * HD * HD;
        int k = q / HD, n = q - k * HD;
        const float* W = (lb == 0) ? w0 : (lb == 1) ? w1 : (lb == 2) ? w2 : w3;
        float v = (lb == 0 && k >= 131) ? 0.f : W[(size_t)k * HD + n];
        __half h = __float2half_rn(v);
        __half l = __float2half_rn(v - __half2float(h));
        g_Wh4[(size_t)lb * HD * HD + (size_t)n * HD + k] = h;
        g_Wl4[(size_t)lb * HD * HD + (size_t)n * HD + k] = l;
    } else {
        int z = idx - asz - bsz;
        if (z < NMAXI * NCHP / 4)
            reinterpret_cast<int4*>(g_histT)[z] = make_int4(0, 0, 0, 0);
    }
}

// ----------------------------- CSR build -----------------------------------
__global__ void k_hist(const int* __restrict__ dst, int E) {
    int e = blockIdx.x * CSZ + threadIdx.x;
    if (threadIdx.x < CSZ && e < E)
        atomicAdd(&g_histT[dst[e] * NCHP + blockIdx.x], 1);
}

__global__ void k_cscan(int N, int nchunk) {
    int w    = (blockIdx.x * blockDim.x + threadIdx.x) >> 5;
    int lane = threadIdx.x & 31;
    if (w >= N) return;
    int* row = g_histT + w * NCHP;
    int run = 0;
    for (int cb = 0; cb < nchunk; cb += 32) {
        int c = cb + lane;
        int v = (c < nchunk) ? row[c] : 0;
        int s = v;
        #pragma unroll
        for (int o = 1; o < 32; o <<= 1) {
            int t = __shfl_up_sync(0xffffffffu, s, o);
            if (lane >= o) s += t;
        }
        if (c < nchunk) row[c] = run + (s - v);
        run += __shfl_sync(0xffffffffu, s, 31);
    }
    if (lane == 0) g_deg[w] = run;
}

__global__ void k_scan(int N) {
    __shared__ int wsum[32];
    int tid = threadIdx.x;
    int CH = (N + 1023) >> 10;
    int start = tid * CH;
    int loc[8];
    int sum = 0;
    #pragma unroll
    for (int i = 0; i < 8; ++i) {
        if (i < CH) {
            int idx = start + i;
            int v = (idx < N) ? g_deg[idx] : 0;
            loc[i] = sum; sum += v;
        }
    }
    int lane = tid & 31, wid = tid >> 5;
    int s = sum;
    #pragma unroll
    for (int o = 1; o < 32; o <<= 1) {
        int t = __shfl_up_sync(0xffffffffu, s, o);
        if (lane >= o) s += t;
    }
    if (lane == 31) wsum[wid] = s;
    __syncthreads();
    if (wid == 0) {
        int v = wsum[lane];
        #pragma unroll
        for (int o = 1; o < 32; o <<= 1) {
            int t = __shfl_up_sync(0xffffffffu, v, o);
            if (lane >= o) v += t;
        }
        wsum[lane] = v;
    }
    __syncthreads();
    int tbase = s - sum + (wid > 0 ? wsum[wid - 1] : 0);
    #pragma unroll
    for (int i = 0; i < 8; ++i) {
        if (i < CH) {
            int idx = start + i;
            if (idx < N) g_base[idx] = tbase + loc[i];
        }
    }
}

__global__ void k_scatter(const int* __restrict__ src, const int* __restrict__ dst,
                          int E) {
    __shared__ int sd[CSZ];
    int c = blockIdx.x, i = threadIdx.x;
    int e = c * CSZ + i;
    int d = -1, s = 0;
    if (e < E) { d = dst[e]; s = src[e]; }
    sd[i] = d;
    __syncthreads();
    if (d >= 0) {
        int rank = 0;
        for (int j = 0; j < i; ++j) rank += (sd[j] == d);
        g_csr[g_base[d] + g_histT[d * NCHP + c] + rank] = s;
    }
}

// --------------------- fp16 2-term HMMA GEMM + fused attn ------------------
constexpr int A_TILE_B = 9216;                  // 64 * 144
constexpr int B_TILE_B = 18432;                 // 128 * 144
constexpr int STAGE_B  = A_TILE_B + B_TILE_B;   // 27648
constexpr int SM_TOTAL = 3 * STAGE_B;           // 82944

__device__ __forceinline__ void load_chunk(uint32_t sb, int buf, int m0, int n0,
                                           int cc, int cpt, int tid, int layer) {
    int sp = cc / cpt;               // 0: A*Wh   1: A*Wl
    int ko = (cc - sp * cpt) * 64;
    const ushort* Ag = (const ushort*)g_A16 + (size_t)m0 * HD + ko;
    const ushort* Bg = (const ushort*)(sp == 1 ? g_Wl4 : g_Wh4)
                       + (size_t)layer * HD * HD + (size_t)n0 * HD + ko;
    uint32_t sa = sb + buf * STAGE_B;
    uint32_t sbb = sa + A_TILE_B;
    #pragma unroll
    for (int t = 0; t < 4; ++t) {
        int task = t * 128 + tid;
        int r = task >> 3, q = task & 7;
        cpa16(sa + r * 144 + q * 16, Ag + (size_t)r * HD + q * 8);
    }
    #pragma unroll
    for (int t = 0; t < 8; ++t) {
        int task = t * 128 + tid;
        int r = task >> 3, q = task & 7;
        cpa16(sbb + r * 144 + q * 16, Bg + (size_t)r * HD + q * 8);
    }
    cpa_commit();
}

__device__ __forceinline__ void ld_frags(uint32_t S, uint32_t a_off,
                                         uint32_t b_off, int ks,
                                         uint32_t a[2][4], uint32_t b[8][2]) {
    uint32_t kb = ks * 32;
    ldsm_x4(a[0][0], a[0][1], a[0][2], a[0][3], S + a_off + kb);
    ldsm_x4(a[1][0], a[1][1], a[1][2], a[1][3], S + a_off + 16 * 144 + kb);
    #pragma unroll
    for (int pr = 0; pr < 4; ++pr)
        ldsm_x4(b[pr * 2][0], b[pr * 2][1], b[pr * 2 + 1][0],
                b[pr * 2 + 1][1], S + b_off + pr * (16 * 144) + kb);
}

__global__ __launch_bounds__(128, 2) void k_mma(int M, int layer, int cpt,
                                                const float* __restrict__ al,
                                                const float* __restrict__ ar) {
    extern __shared__ char smem[];
    uint32_t sb = smem_u32(smem);
    int tid = threadIdx.x, lane = tid & 31, wid = tid >> 5;
    int warp_m = wid & 1, warp_n = wid >> 1;
    int g = lane >> 2, tig = lane & 3;
    int n0 = blockIdx.x * 128, m0 = blockIdx.y * 64;
    int nc = 2 * cpt;

    float acc[2][8][4];
    #pragma unroll
    for (int mt = 0; mt < 2; ++mt)
        #pragma unroll
        for (int nt = 0; nt < 8; ++nt)
            #pragma unroll
            for (int q = 0; q < 4; ++q) acc[mt][nt][q] = 0.f;

    load_chunk(sb, 0, m0, n0, 0, cpt, tid, layer);
    load_chunk(sb, 1, m0, n0, 1, cpt, tid, layer);

    uint32_t a_off = (uint32_t)((warp_m * 32 + (lane & 15)) * 144
                                + (lane >> 4) * 16);
    uint32_t b_off = (uint32_t)(A_TILE_B
                                + (warp_n * 64 + ((lane >> 4) & 1) * 8 + (lane & 7)) * 144
                                + ((lane >> 3) & 1) * 16);

    uint32_t a[2][2][4], b[2][8][2];
    for (int cc = 0; cc < nc; ++cc) {
        if (cc + 1 < nc) cpa_wait1(); else cpa_wait0();
        __syncthreads();
        if (cc + 2 < nc)
            load_chunk(sb, (cc + 2) % 3, m0, n0, cc + 2, cpt, tid, layer);
        uint32_t S = sb + (cc % 3) * STAGE_B;
        ld_frags(S, a_off, b_off, 0, a[0], b[0]);
        #pragma unroll
        for (int ks = 0; ks < 4; ++ks) {
            if (ks < 3)
                ld_frags(S, a_off, b_off, ks + 1, a[(ks + 1) & 1], b[(ks + 1) & 1]);
            #pragma unroll
            for (int mt = 0; mt < 2; ++mt)
                #pragma unroll
                for (int nt = 0; nt < 8; ++nt)
                    mma_f16(acc[mt][nt], a[ks & 1][mt], b[ks & 1][nt]);
        }
    }

    int h = (n0 >> 6) + warp_n;
    const float* alh = al + h * 64;
    const float* arh = ar + h * 64;
    #pragma unroll
    for (int mt = 0; mt < 2; ++mt) {
        int r0 = m0 + warp_m * 32 + mt * 16 + g;
        float el0 = 0.f, el1 = 0.f, er0 = 0.f, er1 = 0.f;
        #pragma unroll
        for (int nt = 0; nt < 8; ++nt) {
            int col = n0 + warp_n * 64 + nt * 8 + tig * 2;
            int d = nt * 8 + tig * 2;
            float av0 = __ldg(&alh[d]), av1 = __ldg(&alh[d + 1]);
            float rv0 = __ldg(&arh[d]), rv1 = __ldg(&arh[d + 1]);
            el0 = fmaf(acc[mt][nt][0], av0, fmaf(acc[mt][nt][1], av1, el0));
            el1 = fmaf(acc[mt][nt][2], av0, fmaf(acc[mt][nt][3], av1, el1));
            er0 = fmaf(acc[mt][nt][0], rv0, fmaf(acc[mt][nt][1], rv1, er0));
            er1 = fmaf(acc[mt][nt][2], rv0, fmaf(acc[mt][nt][3], rv1, er1));
            if (r0 < M)
                *(__half2*)(g_f16 + (size_t)r0 * HD + col) =
                    __floats2half2_rn(acc[mt][nt][0], acc[mt][nt][1]);
            if (r0 + 8 < M)
                *(__half2*)(g_f16 + (size_t)(r0 + 8) * HD + col) =
                    __floats2half2_rn(acc[mt][nt][2], acc[mt][nt][3]);
        }
        el0 += __shfl_xor_sync(0xffffffffu, el0, 1);
        el0 += __shfl_xor_sync(0xffffffffu, el0, 2);
        el1 += __shfl_xor_sync(0xffffffffu, el1, 1);
        el1 += __shfl_xor_sync(0xffffffffu, el1, 2);
        er0 += __shfl_xor_sync(0xffffffffu, er0, 1);
        er0 += __shfl_xor_sync(0xffffffffu, er0, 2);
        er1 += __shfl_xor_sync(0xffffffffu, er1, 1);
        er1 += __shfl_xor_sync(0xffffffffu, er1, 2);
        if (tig == 0) {
            if (r0 < M)     { g_el[r0 * NH + h] = el0;       g_er[r0 * NH + h] = er0; }
            if (r0 + 8 < M) { g_el[(r0 + 8) * NH + h] = el1; g_er[(r0 + 8) * NH + h] = er1; }
        }
    }
}

// ------ edge softmax + aggregation (warp/node, prefetch depth 2) -----------
template <bool FINAL>
__global__ void k_agg(const float* __restrict__ bias, const float* __restrict__ pw,
                      int N) {
    int w    = (blockIdx.x * blockDim.x + threadIdx.x) >> 5;
    int lane = threadIdx.x & 31;
    if (w >= N) return;
    float er_l = (lane < NH) ? g_er[w * NH + lane] : 0.f;
    int b0 = g_base[w], dg = g_deg[w];
    float4 a0 = {0.f, 0.f, 0.f, 0.f}, a1 = a0, a2 = a0;
    float den_l = 0.f;
    int h0 = lane >> 4;

    // depth-2 pipeline: el/features for i, i+1 buffered; csr window i+2, i+3
    float elb[2] = {0.f, 0.f};
    uint2 ub[2][3];
    int sW0 = 0, sW1 = 0;
    if (dg > 0) {
        int s0 = __ldg(&g_csr[b0]);
        if (lane < NH) elb[0] = __ldg(&g_el[s0 * NH + lane]);
        const __half* fr = g_f16 + (size_t)s0 * HD;
        ub[0][0] = *(const uint2*)(fr + lane * 4);
        ub[0][1] = *(const uint2*)(fr + 128 + lane * 4);
        ub[0][2] = *(const uint2*)(fr + 256 + lane * 4);
    }
    if (dg > 1) {
        int s1 = __ldg(&g_csr[b0 + 1]);
        if (lane < NH) elb[1] = __ldg(&g_el[s1 * NH + lane]);
        const __half* fr = g_f16 + (size_t)s1 * HD;
        ub[1][0] = *(const uint2*)(fr + lane * 4);
        ub[1][1] = *(const uint2*)(fr + 128 + lane * 4);
        ub[1][2] = *(const uint2*)(fr + 256 + lane * 4);
    }
    if (dg > 2) sW0 = __ldg(&g_csr[b0 + 2]);
    if (dg > 3) sW1 = __ldg(&g_csr[b0 + 3]);

    for (int p = 0; p < dg; ++p) {
        float el_cur = elb[p & 1];
        uint2 u0 = ub[p & 1][0], u1 = ub[p & 1][1], u2 = ub[p & 1][2];
        // issue loads for edge p+2 using csr value fetched 2 iters ago
        int sLoad = sW0;
        sW0 = sW1;
        if (p + 4 < dg) sW1 = __ldg(&g_csr[b0 + p + 4]);
        if (p + 2 < dg) {
            if (lane < NH) elb[p & 1] = __ldg(&g_el[sLoad * NH + lane]);
            const __half* fr = g_f16 + (size_t)sLoad * HD;
            ub[p & 1][0] = *(const uint2*)(fr + lane * 4);
            ub[p & 1][1] = *(const uint2*)(fr + 128 + lane * 4);
            ub[p & 1][2] = *(const uint2*)(fr + 256 + lane * 4);
        }
        // compute on current operands
        float w_l = 0.f;
        if (lane < NH) {
            float e = el_cur + er_l;
            e = e > 0.f ? e : 0.2f * e;
            w_l = __expf(e);
            den_l += w_l;
        }
        float w0 = __shfl_sync(0xffffffffu, w_l, h0);
        float w1 = __shfl_sync(0xffffffffu, w_l, h0 + 2);
        float w2 = __shfl_sync(0xffffffffu, w_l, h0 + 4);
        float2 p00 = __half22float2(*(const __half2*)&u0.x);
        float2 p01 = __half22float2(*(const __half2*)&u0.y);
        float2 p10 = __half22float2(*(const __half2*)&u1.x);
        float2 p11 = __half22float2(*(const __half2*)&u1.y);
        float2 p20 = __half22float2(*(const __half2*)&u2.x);
        float2 p21 = __half22float2(*(const __half2*)&u2.y);
        a0.x = fmaf(w0, p00.x, a0.x); a0.y = fmaf(w0, p00.y, a0.y);
        a0.z = fmaf(w0, p01.x, a0.z); a0.w = fmaf(w0, p01.y, a0.w);
        a1.x = fmaf(w1, p10.x, a1.x); a1.y = fmaf(w1, p10.y, a1.y);
        a1.z = fmaf(w1, p11.x, a1.z); a1.w = fmaf(w1, p11.y, a1.w);
        a2.x = fmaf(w2, p20.x, a2.x); a2.y = fmaf(w2, p20.y, a2.y);
        a2.z = fmaf(w2, p21.x, a2.z); a2.w = fmaf(w2, p21.y, a2.w);
    }

    float d0 = __shfl_sync(0xffffffffu, den_l, h0);
    float d1 = __shfl_sync(0xffffffffu, den_l, h0 + 2);
    float d2 = __shfl_sync(0xffffffffu, den_l, h0 + 4);
    float i0 = (dg > 0) ? 1.f / d0 : 0.f;
    float i1 = (dg > 0) ? 1.f / d1 : 0.f;
    float i2 = (dg > 0) ? 1.f / d2 : 0.f;
    const float4* b4 = reinterpret_cast<const float4*>(bias);
    float4 bv0 = b4[lane], bv1 = b4[lane + 32], bv2 = b4[lane + 64];
    float4 r0, r1, r2;
    r0.x = a0.x * i0 + bv0.x; r0.y = a0.y * i0 + bv0.y;
    r0.z = a0.z * i0 + bv0.z; r0.w = a0.w * i0 + bv0.w;
    r1.x = a1.x * i1 + bv1.x; r1.y = a1.y * i1 + bv1.y;
    r1.z = a1.z * i1 + bv1.z; r1.w = a1.w * i1 + bv1.w;
    r2.x = a2.x * i2 + bv2.x; r2.y = a2.y * i2 + bv2.y;
    r2.z = a2.z * i2 + bv2.z; r2.w = a2.w * i2 + bv2.w;

    if (!FINAL) {
        r0.x = r0.x > 0.f ? r0.x : expm1f(r0.x);
        r0.y = r0.y > 0.f ? r0.y : expm1f(r0.y);
        r0.z = r0.z > 0.f ? r0.z : expm1f(r0.z);
        r0.w = r0.w > 0.f ? r0.w : expm1f(r0.w);
        r1.x = r1.x > 0.f ? r1.x : expm1f(r1.x);
        r1.y = r1.y > 0.f ? r1.y : expm1f(r1.y);
        r1.z = r1.z > 0.f ? r1.z : expm1f(r1.z);
        r1.w = r1.w > 0.f ? r1.w : expm1f(r1.w);
        r2.x = r2.x > 0.f ? r2.x : expm1f(r2.x);
        r2.y = r2.y > 0.f ? r2.y : expm1f(r2.y);
        r2.z = r2.z > 0.f ? r2.z : expm1f(r2.z);
        r2.w = r2.w > 0.f ? r2.w : expm1f(r2.w);
        uint2* oA = reinterpret_cast<uint2*>(g_A16);
        size_t rb = (size_t)w * 96;
        uint2 v0 = {pack_h2(r0.x, r0.y), pack_h2(r0.z, r0.w)};
        uint2 v1 = {pack_h2(r1.x, r1.y), pack_h2(r1.z, r1.w)};
        uint2 v2 = {pack_h2(r2.x, r2.y), pack_h2(r2.z, r2.w)};
        oA[rb + lane]      = v0;
        oA[rb + lane + 32] = v1;
        oA[rb + lane + 64] = v2;
    } else {
        float pt0 = r0.x + r1.x + r2.x;
        float pt1 = r0.y + r1.y + r2.y;
        float pt2 = r0.z + r1.z + r2.z;
        float pt3 = r0.w + r1.w + r2.w;
        int dbase = (4 * lane) & 63;
        float c1 = pt0 * pw[dbase]     + pt1 * pw[dbase + 1]
                 + pt2 * pw[dbase + 2] + pt3 * pw[dbase + 3];
        float c2 = pt0 * pw[64 + dbase]     + pt1 * pw[64 + dbase + 1]
                 + pt2 * pw[64 + dbase + 2] + pt3 * pw[64 + dbase + 3];
        #pragma unroll
        for (int o = 16; o; o >>= 1) {
            c1 += __shfl_xor_sync(0xffffffffu, c1, o);
            c2 += __shfl_xor_sync(0xffffffffu, c2, o);
        }
        if (lane == 0) {
            g_s1[w] = c1 * (1.f / 6.f);
            g_s2[w] = c2 * (1.f / 6.f);
        }
    }
}

// --------------------------- pairwise output -------------------------------
__device__ __forceinline__ float tanhfast(float x) {
    float xc = fminf(fmaxf(x, -15.f), 15.f);
    float t = __expf(2.f * xc);
    return __fdividef(t - 1.f, t + 1.f);
}

__global__ void k_pair(const float* __restrict__ dis, const float* __restrict__ pw,
                       const float* __restrict__ pb, float* __restrict__ out, int N) {
    int t  = blockIdx.x * blockDim.x + threadIdx.x;
    int i  = blockIdx.y;
    int nq = N >> 2;
    int j4 = t * 2;
    if (j4 >= nq) return;
    float c    = __ldg(&pw[128]);
    float base = g_s2[i] + __ldg(pb);
    const float4* dp = reinterpret_cast<const float4*>(dis) + (size_t)i * nq;
    const float4* sp = reinterpret_cast<const float4*>(g_s1);
    float4*       op = reinterpret_cast<float4*>(out) + (size_t)i * nq;
    float4 d0 = dp[j4], d1 = dp[j4 + 1];
    float4 s0 = sp[j4], s1 = sp[j4 + 1];
    float4 r0, r1;
    r0.x = tanhfast(base + s0.x + d0.x * c);
    r0.y = tanhfast(base + s0.y + d0.y * c);
    r0.z = tanhfast(base + s0.z + d0.z * c);
    r0.w = tanhfast(base + s0.w + d0.w * c);
    r1.x = tanhfast(base + s1.x + d1.x * c);
    r1.y = tanhfast(base + s1.y + d1.y * c);
    r1.z = tanhfast(base + s1.z + d1.z * c);
    r1.w = tanhfast(base + s1.w + d1.w * c);
    op[j4]     = r0;
    op[j4 + 1] = r1;
}

// ------------------------------- launcher -----------------------------------
extern "C" void kernel_launch(void* const* d_in, const int* in_sizes, int n_in,
                              void* d_out, int out_size) {
    const float* nfeats = (const float*)d_in[0];
    const float* dis    = (const float*)d_in[1];
    const int*   src    = (const int*)d_in[2];
    const int*   dst    = (const int*)d_in[3];
    const float* pw     = (const float*)d_in[20];
    const float* pb     = (const float*)d_in[21];

    const int IN = 131;
    int N = in_sizes[0] / IN;             // 5000
    int E = in_sizes[2];                  // 160000
    int nchunk = (E + CSZ - 1) / CSZ;
    int Mpad = ((N + 127) / 128) * 128;   // 5120

    cudaFuncSetAttribute(k_mma, cudaFuncAttributeMaxDynamicSharedMemorySize,
                         SM_TOTAL);

    dim3 gg(HD / 128, Mpad / 64);         // (3, 80) = 240 CTAs
    int nwb = (N * 32 + 255) / 256;

    // conversions + histogram zero
    int conv_elems = Mpad * HD + 4 * HD * HD + NMAXI * NCHP / 4;
    k_convAB<<<(conv_elems + 255) / 256, 256>>>(
        nfeats, (const float*)d_in[4], (const float*)d_in[8],
        (const float*)d_in[12], (const float*)d_in[16], N, Mpad);

    // CSR build interleaved with layer-0 GEMM (k_mma at profiled index 3)
    k_hist<<<nchunk, CSZ>>>(dst, E);
    k_cscan<<<(N * 32 + 255) / 256, 256>>>(N, nchunk);
    k_mma<<<gg, 128, SM_TOTAL>>>(N, 0, 3,
        (const float*)d_in[5], (const float*)d_in[6]);
    k_scan<<<1, 1024>>>(N);
    k_scatter<<<nchunk, CSZ>>>(src, dst, E);

    for (int l = 0; l < 4; ++l) {
        const float* b = (const float*)d_in[7 + 4 * l];
        if (l > 0) {
            const float* al = (const float*)d_in[5 + 4 * l];
            const float* ar = (const float*)d_in[6 + 4 * l];
            k_mma<<<gg, 128, SM_TOTAL>>>(N, l, 6, al, ar);
        }
        if (l < 3) k_agg<false><<<nwb, 256>>>(b, nullptr, N);
        else       k_agg<true><<<nwb, 256>>>(b, pw, N);
    }

    int nq = N / 4;
    dim3 gp((nq / 2 + 255) / 256, N);
    k_pair<<<gp, 256>>>(dis, pw, pb, (float*)d_out, N);
}

// round 15
// speedup vs baseline: 1.1185x; 1.1185x over previous
#include <cuda_runtime.h>
#include <cuda_bf16.h>
#include <cuda_fp16.h>
#include <cstdint>

// ---------------------------------------------------------------------------
// GAT (4 layers) + pairwise tanh for GB300 (sm_103a harness, compute_103 PTX).
// GEMM: fp16 HMMA, A single fp16, W fp16 hi/lo split (C = A*Wh + A*Wl).
// block 64x128, 128 thr, 4 warps 32x64, ldmatrix.x4 + reg fragment prefetch,
// 3-stage cp.async pipeline, fused attention-dot epilogue, fp16 f.
// Aggregation: 1 warp/node, prefetch depth 1 (R12 structure, frozen).
// CSR: node-major histogram + warp scans; row bases via atomic allocation
// (per-node edge order unchanged -> output deterministic).
// ---------------------------------------------------------------------------

constexpr int HD  = 384;        // H*D
constexpr int NH  = 6;          // heads
constexpr int NMAXI = 5120;     // max nodes (actual 5000), mult of 128
constexpr int EMAXI = 163840;
constexpr int CSZ   = 320;      // edges per sort chunk
constexpr int NCHP  = 512;      // chunk stride (chunks actual 500)

// ------------------------- device scratch ----------------------------------
__device__ __align__(16) __half g_f16[NMAXI * HD];           // fp16 GEMM out
__device__ __align__(16) __half g_A16[NMAXI * HD];           // fp16 layer input
__device__ __align__(16) __half g_Wh4[4 * HD * HD];          // W^T hi [l][n][k]
__device__ __align__(16) __half g_Wl4[4 * HD * HD];          // W^T lo
__device__ float g_el[NMAXI * NH];
__device__ float g_er[NMAXI * NH];
__device__ __align__(16) int g_histT[NMAXI * NCHP];          // node-major counts
__device__ int   g_base[NMAXI];
__device__ int   g_deg[NMAXI];
__device__ int   g_csr[EMAXI];
__device__ int   g_ecnt;                                     // edge allocator
__device__ __align__(16) float g_s1[NMAXI];
__device__ __align__(16) float g_s2[NMAXI];

// --------------------------- helpers ----------------------------------------
__device__ __forceinline__ uint32_t smem_u32(const void* p) {
    uint32_t a;
    asm("{ .reg .u64 t; cvta.to.shared.u64 t, %1; cvt.u32.u64 %0, t; }"
        : "=r"(a) : "l"(p));
    return a;
}
__device__ __forceinline__ void cpa16(uint32_t s, const void* g) {
    asm volatile("cp.async.ca.shared.global [%0], [%1], 16;"
                 :: "r"(s), "l"(g) : "memory");
}
__device__ __forceinline__ void cpa_commit() {
    asm volatile("cp.async.commit_group;" ::: "memory");
}
__device__ __forceinline__ void cpa_wait0() {
    asm volatile("cp.async.wait_group 0;" ::: "memory");
}
__device__ __forceinline__ void cpa_wait1() {
    asm volatile("cp.async.wait_group 1;" ::: "memory");
}
__device__ __forceinline__ void mma_f16(float* d, const uint32_t* a,
                                        const uint32_t* b) {
    asm volatile(
        "mma.sync.aligned.m16n8k16.row.col.f32.f16.f16.f32 "
        "{%0,%1,%2,%3}, {%4,%5,%6,%7}, {%8,%9}, {%0,%1,%2,%3};"
        : "+f"(d[0]), "+f"(d[1]), "+f"(d[2]), "+f"(d[3])
        : "r"(a[0]), "r"(a[1]), "r"(a[2]), "r"(a[3]), "r"(b[0]), "r"(b[1]));
}
__device__ __forceinline__ void ldsm_x4(uint32_t& r0, uint32_t& r1,
                                        uint32_t& r2, uint32_t& r3,
                                        uint32_t addr) {
    asm volatile("ldmatrix.sync.aligned.m8n8.x4.shared.b16 {%0,%1,%2,%3}, [%4];"
                 : "=r"(r0), "=r"(r1), "=r"(r2), "=r"(r3) : "r"(addr));
}
__device__ __forceinline__ uint32_t pack_h2(float a, float b) {
    __half2 h = __floats2half2_rn(a, b);
    return *reinterpret_cast<uint32_t*>(&h);
}

// -------------- conversions + histogram zero (one kernel, runs first) -------
__global__ void k_convAB(const float* __restrict__ nfeats,
                         const float* __restrict__ w0, const float* __restrict__ w1,
                         const float* __restrict__ w2, const float* __restrict__ w3,
                         int M, int Mpad) {
    int idx = blockIdx.x * blockDim.x + threadIdx.x;
    if (idx == 0) g_ecnt = 0;
    int asz = Mpad * HD;
    int bsz = 4 * HD * HD;
    if (idx < asz) {
        int m = idx / HD, k = idx - m * HD;
        float v = (m < M && k < 131) ? nfeats[(size_t)m * 131 + k] : 0.f;
        g_A16[idx] = __float2half_rn(v);
    } else if (idx < asz + bsz) {
        int r = idx - asz;
        int lb = r / (HD * HD);
        int q = r - lb * HD * HD;
        int k = q / HD, n = q - k * HD;
        const float* W = (lb == 0) ? w0 : (lb == 1) ? w1 : (lb == 2) ? w2 : w3;
        float v = (lb == 0 && k >= 131) ? 0.f : W[(size_t)k * HD + n];
        __half h = __float2half_rn(v);
        __half l = __float2half_rn(v - __half2float(h));
        g_Wh4[(size_t)lb * HD * HD + (size_t)n * HD + k] = h;
        g_Wl4[(size_t)lb * HD * HD + (size_t)n * HD + k] = l;
    } else {
        int z = idx - asz - bsz;
        if (z < NMAXI * NCHP / 4)
            reinterpret_cast<int4*>(g_histT)[z] = make_int4(0, 0, 0, 0);
    }
}

// ----------------------------- CSR build -----------------------------------
__global__ void k_hist(const int* __restrict__ dst, int E) {
    int e = blockIdx.x * CSZ + threadIdx.x;
    if (threadIdx.x < CSZ && e < E)
        atomicAdd(&g_histT[dst[e] * NCHP + blockIdx.x], 1);
}

// warp-per-node chunk scan + atomic row-base allocation (replaces k_scan;
// base placement may vary run-to-run but per-node edge ORDER is fixed, so
// all reductions -> identical output).
__global__ void k_cscan(int N, int nchunk) {
    int w    = (blockIdx.x * blockDim.x + threadIdx.x) >> 5;
    int lane = threadIdx.x & 31;
    if (w >= N) return;
    int* row = g_histT + w * NCHP;
    int run = 0;
    for (int cb = 0; cb < nchunk; cb += 32) {
        int c = cb + lane;
        int v = (c < nchunk) ? row[c] : 0;
        int s = v;
        #pragma unroll
        for (int o = 1; o < 32; o <<= 1) {
            int t = __shfl_up_sync(0xffffffffu, s, o);
            if (lane >= o) s += t;
        }
        if (c < nchunk) row[c] = run + (s - v);
        run += __shfl_sync(0xffffffffu, s, 31);
    }
    if (lane == 0) {
        g_deg[w] = run;
        g_base[w] = atomicAdd(&g_ecnt, run);
    }
}

__global__ void k_scatter(const int* __restrict__ src, const int* __restrict__ dst,
                          int E) {
    __shared__ int sd[CSZ];
    int c = blockIdx.x, i = threadIdx.x;
    int e = c * CSZ + i;
    int d = -1, s = 0;
    if (e < E) { d = dst[e]; s = src[e]; }
    sd[i] = d;
    __syncthreads();
    if (d >= 0) {
        int rank = 0;
        for (int j = 0; j < i; ++j) rank += (sd[j] == d);
        g_csr[g_base[d] + g_histT[d * NCHP + c] + rank] = s;
    }
}

// --------------------- fp16 2-term HMMA GEMM + fused attn ------------------
constexpr int A_TILE_B = 9216;                  // 64 * 144
constexpr int B_TILE_B = 18432;                 // 128 * 144
constexpr int STAGE_B  = A_TILE_B + B_TILE_B;   // 27648
constexpr int SM_TOTAL = 3 * STAGE_B;           // 82944

__device__ __forceinline__ void load_chunk(uint32_t sb, int buf, int m0, int n0,
                                           int cc, int cpt, int tid, int layer) {
    int sp = cc / cpt;               // 0: A*Wh   1: A*Wl
    int ko = (cc - sp * cpt) * 64;
    const ushort* Ag = (const ushort*)g_A16 + (size_t)m0 * HD + ko;
    const ushort* Bg = (const ushort*)(sp == 1 ? g_Wl4 : g_Wh4)
                       + (size_t)layer * HD * HD + (size_t)n0 * HD + ko;
    uint32_t sa = sb + buf * STAGE_B;
    uint32_t sbb = sa + A_TILE_B;
    #pragma unroll
    for (int t = 0; t < 4; ++t) {
        int task = t * 128 + tid;
        int r = task >> 3, q = task & 7;
        cpa16(sa + r * 144 + q * 16, Ag + (size_t)r * HD + q * 8);
    }
    #pragma unroll
    for (int t = 0; t < 8; ++t) {
        int task = t * 128 + tid;
        int r = task >> 3, q = task & 7;
        cpa16(sbb + r * 144 + q * 16, Bg + (size_t)r * HD + q * 8);
    }
    cpa_commit();
}

__device__ __forceinline__ void ld_frags(uint32_t S, uint32_t a_off,
                                         uint32_t b_off, int ks,
                                         uint32_t a[2][4], uint32_t b[8][2]) {
    uint32_t kb = ks * 32;
    ldsm_x4(a[0][0], a[0][1], a[0][2], a[0][3], S + a_off + kb);
    ldsm_x4(a[1][0], a[1][1], a[1][2], a[1][3], S + a_off + 16 * 144 + kb);
    #pragma unroll
    for (int pr = 0; pr < 4; ++pr)
        ldsm_x4(b[pr * 2][0], b[pr * 2][1], b[pr * 2 + 1][0],
                b[pr * 2 + 1][1], S + b_off + pr * (16 * 144) + kb);
}

__global__ __launch_bounds__(128, 2) void k_mma(int M, int layer, int cpt,
                                                const float* __restrict__ al,
                                                const float* __restrict__ ar) {
    extern __shared__ char smem[];
    uint32_t sb = smem_u32(smem);
    int tid = threadIdx.x, lane = tid & 31, wid = tid >> 5;
    int warp_m = wid & 1, warp_n = wid >> 1;
    int g = lane >> 2, tig = lane & 3;
    int n0 = blockIdx.x * 128, m0 = blockIdx.y * 64;
    int nc = 2 * cpt;

    float acc[2][8][4];
    #pragma unroll
    for (int mt = 0; mt < 2; ++mt)
        #pragma unroll
        for (int nt = 0; nt < 8; ++nt)
            #pragma unroll
            for (int q = 0; q < 4; ++q) acc[mt][nt][q] = 0.f;

    load_chunk(sb, 0, m0, n0, 0, cpt, tid, layer);
    load_chunk(sb, 1, m0, n0, 1, cpt, tid, layer);

    uint32_t a_off = (uint32_t)((warp_m * 32 + (lane & 15)) * 144
                                + (lane >> 4) * 16);
    uint32_t b_off = (uint32_t)(A_TILE_B
                                + (warp_n * 64 + ((lane >> 4) & 1) * 8 + (lane & 7)) * 144
                                + ((lane >> 3) & 1) * 16);

    uint32_t a[2][2][4], b[2][8][2];
    for (int cc = 0; cc < nc; ++cc) {
        if (cc + 1 < nc) cpa_wait1(); else cpa_wait0();
        __syncthreads();
        if (cc + 2 < nc)
            load_chunk(sb, (cc + 2) % 3, m0, n0, cc + 2, cpt, tid, layer);
        uint32_t S = sb + (cc % 3) * STAGE_B;
        ld_frags(S, a_off, b_off, 0, a[0], b[0]);
        #pragma unroll
        for (int ks = 0; ks < 4; ++ks) {
            if (ks < 3)
                ld_frags(S, a_off, b_off, ks + 1, a[(ks + 1) & 1], b[(ks + 1) & 1]);
            #pragma unroll
            for (int mt = 0; mt < 2; ++mt)
                #pragma unroll
                for (int nt = 0; nt < 8; ++nt)
                    mma_f16(acc[mt][nt], a[ks & 1][mt], b[ks & 1][nt]);
        }
    }

    int h = (n0 >> 6) + warp_n;
    const float* alh = al + h * 64;
    const float* arh = ar + h * 64;
    #pragma unroll
    for (int mt = 0; mt < 2; ++mt) {
        int r0 = m0 + warp_m * 32 + mt * 16 + g;
        float el0 = 0.f, el1 = 0.f, er0 = 0.f, er1 = 0.f;
        #pragma unroll
        for (int nt = 0; nt < 8; ++nt) {
            int col = n0 + warp_n * 64 + nt * 8 + tig * 2;
            int d = nt * 8 + tig * 2;
            float av0 = __ldg(&alh[d]), av1 = __ldg(&alh[d + 1]);
            float rv0 = __ldg(&arh[d]), rv1 = __ldg(&arh[d + 1]);
            el0 = fmaf(acc[mt][nt][0], av0, fmaf(acc[mt][nt][1], av1, el0));
            el1 = fmaf(acc[mt][nt][2], av0, fmaf(acc[mt][nt][3], av1, el1));
            er0 = fmaf(acc[mt][nt][0], rv0, fmaf(acc[mt][nt][1], rv1, er0));
            er1 = fmaf(acc[mt][nt][2], rv0, fmaf(acc[mt][nt][3], rv1, er1));
            if (r0 < M)
                *(__half2*)(g_f16 + (size_t)r0 * HD + col) =
                    __floats2half2_rn(acc[mt][nt][0], acc[mt][nt][1]);
            if (r0 + 8 < M)
                *(__half2*)(g_f16 + (size_t)(r0 + 8) * HD + col) =
                    __floats2half2_rn(acc[mt][nt][2], acc[mt][nt][3]);
        }
        el0 += __shfl_xor_sync(0xffffffffu, el0, 1);
        el0 += __shfl_xor_sync(0xffffffffu, el0, 2);
        el1 += __shfl_xor_sync(0xffffffffu, el1, 1);
        el1 += __shfl_xor_sync(0xffffffffu, el1, 2);
        er0 += __shfl_xor_sync(0xffffffffu, er0, 1);
        er0 += __shfl_xor_sync(0xffffffffu, er0, 2);
        er1 += __shfl_xor_sync(0xffffffffu, er1, 1);
        er1 += __shfl_xor_sync(0xffffffffu, er1, 2);
        if (tig == 0) {
            if (r0 < M)     { g_el[r0 * NH + h] = el0;       g_er[r0 * NH + h] = er0; }
            if (r0 + 8 < M) { g_el[(r0 + 8) * NH + h] = el1; g_er[(r0 + 8) * NH + h] = er1; }
        }
    }
}

// ------ edge softmax + aggregation (warp/node, depth-1 pipeline, R12) ------
template <bool FINAL>
__global__ void k_agg(const float* __restrict__ bias, const float* __restrict__ pw,
                      int N) {
    int w    = (blockIdx.x * blockDim.x + threadIdx.x) >> 5;
    int lane = threadIdx.x & 31;
    if (w >= N) return;
    float er_l = (lane < NH) ? g_er[w * NH + lane] : 0.f;
    int b0 = g_base[w], dg = g_deg[w];
    float4 a0 = {0.f, 0.f, 0.f, 0.f}, a1 = a0, a2 = a0;
    float den_l = 0.f;
    int h0 = lane >> 4;

    int sA = (dg > 0) ? __ldg(&g_csr[b0])     : 0;
    int sB = (dg > 1) ? __ldg(&g_csr[b0 + 1]) : 0;
    float elA = 0.f;
    uint2 u0A = {0, 0}, u1A = {0, 0}, u2A = {0, 0};
    if (dg > 0) {
        if (lane < NH) elA = __ldg(&g_el[sA * NH + lane]);
        const __half* fr = g_f16 + (size_t)sA * HD;
        u0A = *(const uint2*)(fr + lane * 4);
        u1A = *(const uint2*)(fr + 128 + lane * 4);
        u2A = *(const uint2*)(fr + 256 + lane * 4);
    }

    for (int p = 0; p < dg; ++p) {
        float el_cur = elA;
        uint2 u0 = u0A, u1 = u1A, u2 = u2A;
        int sN = sA = sB;
        if (p + 2 < dg) sB = __ldg(&g_csr[b0 + p + 2]);
        if (p + 1 < dg) {
            if (lane < NH) elA = __ldg(&g_el[sN * NH + lane]);
            const __half* fr = g_f16 + (size_t)sN * HD;
            u0A = *(const uint2*)(fr + lane * 4);
            u1A = *(const uint2*)(fr + 128 + lane * 4);
            u2A = *(const uint2*)(fr + 256 + lane * 4);
        }
        float w_l = 0.f;
        if (lane < NH) {
            float e = el_cur + er_l;
            e = e > 0.f ? e : 0.2f * e;
            w_l = __expf(e);
            den_l += w_l;
        }
        float w0 = __shfl_sync(0xffffffffu, w_l, h0);
        float w1 = __shfl_sync(0xffffffffu, w_l, h0 + 2);
        float w2 = __shfl_sync(0xffffffffu, w_l, h0 + 4);
        float2 p00 = __half22float2(*(const __half2*)&u0.x);
        float2 p01 = __half22float2(*(const __half2*)&u0.y);
        float2 p10 = __half22float2(*(const __half2*)&u1.x);
        float2 p11 = __half22float2(*(const __half2*)&u1.y);
        float2 p20 = __half22float2(*(const __half2*)&u2.x);
        float2 p21 = __half22float2(*(const __half2*)&u2.y);
        a0.x = fmaf(w0, p00.x, a0.x); a0.y = fmaf(w0, p00.y, a0.y);
        a0.z = fmaf(w0, p01.x, a0.z); a0.w = fmaf(w0, p01.y, a0.w);
        a1.x = fmaf(w1, p10.x, a1.x); a1.y = fmaf(w1, p10.y, a1.y);
        a1.z = fmaf(w1, p11.x, a1.z); a1.w = fmaf(w1, p11.y, a1.w);
        a2.x = fmaf(w2, p20.x, a2.x); a2.y = fmaf(w2, p20.y, a2.y);
        a2.z = fmaf(w2, p21.x, a2.z); a2.w = fmaf(w2, p21.y, a2.w);
    }

    float d0 = __shfl_sync(0xffffffffu, den_l, h0);
    float d1 = __shfl_sync(0xffffffffu, den_l, h0 + 2);
    float d2 = __shfl_sync(0xffffffffu, den_l, h0 + 4);
    float i0 = (dg > 0) ? 1.f / d0 : 0.f;
    float i1 = (dg > 0) ? 1.f / d1 : 0.f;
    float i2 = (dg > 0) ? 1.f / d2 : 0.f;
    const float4* b4 = reinterpret_cast<const float4*>(bias);
    float4 bv0 = b4[lane], bv1 = b4[lane + 32], bv2 = b4[lane + 64];
    float4 r0, r1, r2;
    r0.x = a0.x * i0 + bv0.x; r0.y = a0.y * i0 + bv0.y;
    r0.z = a0.z * i0 + bv0.z; r0.w = a0.w * i0 + bv0.w;
    r1.x = a1.x * i1 + bv1.x; r1.y = a1.y * i1 + bv1.y;
    r1.z = a1.z * i1 + bv1.z; r1.w = a1.w * i1 + bv1.w;
    r2.x = a2.x * i2 + bv2.x; r2.y = a2.y * i2 + bv2.y;
    r2.z = a2.z * i2 + bv2.z; r2.w = a2.w * i2 + bv2.w;

    if (!FINAL) {
        r0.x = r0.x > 0.f ? r0.x : expm1f(r0.x);
        r0.y = r0.y > 0.f ? r0.y : expm1f(r0.y);
        r0.z = r0.z > 0.f ? r0.z : expm1f(r0.z);
        r0.w = r0.w > 0.f ? r0.w : expm1f(r0.w);
        r1.x = r1.x > 0.f ? r1.x : expm1f(r1.x);
        r1.y = r1.y > 0.f ? r1.y : expm1f(r1.y);
        r1.z = r1.z > 0.f ? r1.z : expm1f(r1.z);
        r1.w = r1.w > 0.f ? r1.w : expm1f(r1.w);
        r2.x = r2.x > 0.f ? r2.x : expm1f(r2.x);
        r2.y = r2.y > 0.f ? r2.y : expm1f(r2.y);
        r2.z = r2.z > 0.f ? r2.z : expm1f(r2.z);
        r2.w = r2.w > 0.f ? r2.w : expm1f(r2.w);
        uint2* oA = reinterpret_cast<uint2*>(g_A16);
        size_t rb = (size_t)w * 96;
        uint2 v0 = {pack_h2(r0.x, r0.y), pack_h2(r0.z, r0.w)};
        uint2 v1 = {pack_h2(r1.x, r1.y), pack_h2(r1.z, r1.w)};
        uint2 v2 = {pack_h2(r2.x, r2.y), pack_h2(r2.z, r2.w)};
        oA[rb + lane]      = v0;
        oA[rb + lane + 32] = v1;
        oA[rb + lane + 64] = v2;
    } else {
        float pt0 = r0.x + r1.x + r2.x;
        float pt1 = r0.y + r1.y + r2.y;
        float pt2 = r0.z + r1.z + r2.z;
        float pt3 = r0.w + r1.w + r2.w;
        int dbase = (4 * lane) & 63;
        float c1 = pt0 * pw[dbase]     + pt1 * pw[dbase + 1]
                 + pt2 * pw[dbase + 2] + pt3 * pw[dbase + 3];
        float c2 = pt0 * pw[64 + dbase]     + pt1 * pw[64 + dbase + 1]
                 + pt2 * pw[64 + dbase + 2] + pt3 * pw[64 + dbase + 3];
        #pragma unroll
        for (int o = 16; o; o >>= 1) {
            c1 += __shfl_xor_sync(0xffffffffu, c1, o);
            c2 += __shfl_xor_sync(0xffffffffu, c2, o);
        }
        if (lane == 0) {
            g_s1[w] = c1 * (1.f / 6.f);
            g_s2[w] = c2 * (1.f / 6.f);
        }
    }
}

// --------------------------- pairwise output -------------------------------
__device__ __forceinline__ float tanhfast(float x) {
    float xc = fminf(fmaxf(x, -15.f), 15.f);
    float t = __expf(2.f * xc);
    return __fdividef(t - 1.f, t + 1.f);
}

__global__ void k_pair(const float* __restrict__ dis, const float* __restrict__ pw,
                       const float* __restrict__ pb, float* __restrict__ out, int N) {
    int t  = blockIdx.x * blockDim.x + threadIdx.x;
    int i  = blockIdx.y;
    int nq = N >> 2;
    int j4 = t * 2;
    if (j4 >= nq) return;
    float c    = __ldg(&pw[128]);
    float base = g_s2[i] + __ldg(pb);
    const float4* dp = reinterpret_cast<const float4*>(dis) + (size_t)i * nq;
    const float4* sp = reinterpret_cast<const float4*>(g_s1);
    float4*       op = reinterpret_cast<float4*>(out) + (size_t)i * nq;
    float4 d0 = dp[j4], d1 = dp[j4 + 1];
    float4 s0 = sp[j4], s1 = sp[j4 + 1];
    float4 r0, r1;
    r0.x = tanhfast(base + s0.x + d0.x * c);
    r0.y = tanhfast(base + s0.y + d0.y * c);
    r0.z = tanhfast(base + s0.z + d0.z * c);
    r0.w = tanhfast(base + s0.w + d0.w * c);
    r1.x = tanhfast(base + s1.x + d1.x * c);
    r1.y = tanhfast(base + s1.y + d1.y * c);
    r1.z = tanhfast(base + s1.z + d1.z * c);
    r1.w = tanhfast(base + s1.w + d1.w * c);
    op[j4]     = r0;
    op[j4 + 1] = r1;
}

// ------------------------------- launcher -----------------------------------
extern "C" void kernel_launch(void* const* d_in, const int* in_sizes, int n_in,
                              void* d_out, int out_size) {
    const float* nfeats = (const float*)d_in[0];
    const float* dis    = (const float*)d_in[1];
    const int*   src    = (const int*)d_in[2];
    const int*   dst    = (const int*)d_in[3];
    const float* pw     = (const float*)d_in[20];
    const float* pb     = (const float*)d_in[21];

    const int IN = 131;
    int N = in_sizes[0] / IN;             // 5000
    int E = in_sizes[2];                  // 160000
    int nchunk = (E + CSZ - 1) / CSZ;
    int Mpad = ((N + 127) / 128) * 128;   // 5120

    cudaFuncSetAttribute(k_mma, cudaFuncAttributeMaxDynamicSharedMemorySize,
                         SM_TOTAL);

    dim3 gg(HD / 128, Mpad / 64);         // (3, 80) = 240 CTAs
    int nwb = (N * 32 + 255) / 256;

    // conversions + histogram zero + edge-allocator zero
    int conv_elems = Mpad * HD + 4 * HD * HD + NMAXI * NCHP / 4;
    k_convAB<<<(conv_elems + 255) / 256, 256>>>(
        nfeats, (const float*)d_in[4], (const float*)d_in[8],
        (const float*)d_in[12], (const float*)d_in[16], N, Mpad);

    // CSR build interleaved with layer-0 GEMM (k_mma at profiled index 3)
    k_hist<<<nchunk, CSZ>>>(dst, E);
    k_cscan<<<(N * 32 + 255) / 256, 256>>>(N, nchunk);
    k_mma<<<gg, 128, SM_TOTAL>>>(N, 0, 3,
        (const float*)d_in[5], (const float*)d_in[6]);
    k_scatter<<<nchunk, CSZ>>>(src, dst, E);

    for (int l = 0; l < 4; ++l) {
        const float* b = (const float*)d_in[7 + 4 * l];
        if (l > 0) {
            const float* al = (const float*)d_in[5 + 4 * l];
            const float* ar = (const float*)d_in[6 + 4 * l];
            k_mma<<<gg, 128, SM_TOTAL>>>(N, l, 6, al, ar);
        }
        if (l < 3) k_agg<false><<<nwb, 256>>>(b, nullptr, N);
        else       k_agg<true><<<nwb, 256>>>(b, pw, N);
    }

    int nq = N / 4;
    dim3 gp((nq / 2 + 255) / 256, N);
    k_pair<<<gp, 256>>>(dis, pw, pb, (float*)d_out, N);
}

// round 16
// speedup vs baseline: 1.1215x; 1.0027x over previous
#include <cuda_runtime.h>
#include <cuda_bf16.h>
#include <cuda_fp16.h>
#include <cstdint>

// ---------------------------------------------------------------------------
// GAT (4 layers) + pairwise tanh for GB300 (sm_103a harness, compute_103 PTX).
// GEMM: fp16 HMMA, A single fp16, W fp16 hi/lo split (C = A*Wh + A*Wl).
// block 64x128, 128 thr, 4 warps 32x64, ldmatrix.x4 + reg fragment prefetch,
// 3-stage cp.async pipeline, fused attention-dot epilogue, fp16 f.
// Aggregation: 1 warp/node, depth-1 pipeline (frozen R12 structure).
// CSR: node-major histogram + warp scans, atomic row-base allocation.
// NEW: CSR chain runs on a forked stream, overlapping conv + layer-0 GEMM.
// ---------------------------------------------------------------------------

constexpr int HD  = 384;        // H*D
constexpr int NH  = 6;          // heads
constexpr int NMAXI = 5120;     // max nodes (actual 5000), mult of 128
constexpr int EMAXI = 163840;
constexpr int CSZ   = 320;      // edges per sort chunk
constexpr int NCHP  = 512;      // chunk stride (chunks actual 500)

// ------------------------- device scratch ----------------------------------
__device__ __align__(16) __half g_f16[NMAXI * HD];           // fp16 GEMM out
__device__ __align__(16) __half g_A16[NMAXI * HD];           // fp16 layer input
__device__ __align__(16) __half g_Wh4[4 * HD * HD];          // W^T hi [l][n][k]
__device__ __align__(16) __half g_Wl4[4 * HD * HD];          // W^T lo
__device__ float g_el[NMAXI * NH];
__device__ float g_er[NMAXI * NH];
__device__ __align__(16) int g_histT[NMAXI * NCHP];          // node-major counts
__device__ int   g_base[NMAXI];
__device__ int   g_deg[NMAXI];
__device__ int   g_csr[EMAXI];
__device__ int   g_ecnt;                                     // edge allocator
__device__ __align__(16) float g_s1[NMAXI];
__device__ __align__(16) float g_s2[NMAXI];

// --------------------------- helpers ----------------------------------------
__device__ __forceinline__ uint32_t smem_u32(const void* p) {
    uint32_t a;
    asm("{ .reg .u64 t; cvta.to.shared.u64 t, %1; cvt.u32.u64 %0, t; }"
        : "=r"(a) : "l"(p));
    return a;
}
__device__ __forceinline__ void cpa16(uint32_t s, const void* g) {
    asm volatile("cp.async.ca.shared.global [%0], [%1], 16;"
                 :: "r"(s), "l"(g) : "memory");
}
__device__ __forceinline__ void cpa_commit() {
    asm volatile("cp.async.commit_group;" ::: "memory");
}
__device__ __forceinline__ void cpa_wait0() {
    asm volatile("cp.async.wait_group 0;" ::: "memory");
}
__device__ __forceinline__ void cpa_wait1() {
    asm volatile("cp.async.wait_group 1;" ::: "memory");
}
__device__ __forceinline__ void mma_f16(float* d, const uint32_t* a,
                                        const uint32_t* b) {
    asm volatile(
        "mma.sync.aligned.m16n8k16.row.col.f32.f16.f16.f32 "
        "{%0,%1,%2,%3}, {%4,%5,%6,%7}, {%8,%9}, {%0,%1,%2,%3};"
        : "+f"(d[0]), "+f"(d[1]), "+f"(d[2]), "+f"(d[3])
        : "r"(a[0]), "r"(a[1]), "r"(a[2]), "r"(a[3]), "r"(b[0]), "r"(b[1]));
}
__device__ __forceinline__ void ldsm_x4(uint32_t& r0, uint32_t& r1,
                                        uint32_t& r2, uint32_t& r3,
                                        uint32_t addr) {
    asm volatile("ldmatrix.sync.aligned.m8n8.x4.shared.b16 {%0,%1,%2,%3}, [%4];"
                 : "=r"(r0), "=r"(r1), "=r"(r2), "=r"(r3) : "r"(addr));
}
__device__ __forceinline__ uint32_t pack_h2(float a, float b) {
    __half2 h = __floats2half2_rn(a, b);
    return *reinterpret_cast<uint32_t*>(&h);
}

// ---------------- conversions (A fp16 + W hi/lo splits) ---------------------
__global__ void k_convAB(const float* __restrict__ nfeats,
                         const float* __restrict__ w0, const float* __restrict__ w1,
                         const float* __restrict__ w2, const float* __restrict__ w3,
                         int M, int Mpad) {
    int idx = blockIdx.x * blockDim.x + threadIdx.x;
    int asz = Mpad * HD;
    int bsz = 4 * HD * HD;
    if (idx < asz) {
        int m = idx / HD, k = idx - m * HD;
        float v = (m < M && k < 131) ? nfeats[(size_t)m * 131 + k] : 0.f;
        g_A16[idx] = __float2half_rn(v);
    } else if (idx < asz + bsz) {
        int r = idx - asz;
        int lb = r / (HD * HD);
        int q = r - lb * HD * HD;
        int k = q / HD, n = q - k * HD;
        const float* W = (lb == 0) ? w0 : (lb == 1) ? w1 : (lb == 2) ? w2 : w3;
        float v = (lb == 0 && k >= 131) ? 0.f : W[(size_t)k * HD + n];
        __half h = __float2half_rn(v);
        __half l = __float2half_rn(v - __half2float(h));
        g_Wh4[(size_t)lb * HD * HD + (size_t)n * HD + k] = h;
        g_Wl4[(size_t)lb * HD * HD + (size_t)n * HD + k] = l;
    }
}

// ----------------------------- CSR build (stream 2) -------------------------
__global__ void k_zero() {
    int i = blockIdx.x * blockDim.x + threadIdx.x;
    if (i == 0) g_ecnt = 0;
    if (i < NMAXI * NCHP / 4)
        reinterpret_cast<int4*>(g_histT)[i] = make_int4(0, 0, 0, 0);
}

__global__ void k_hist(const int* __restrict__ dst, int E) {
    int e = blockIdx.x * CSZ + threadIdx.x;
    if (threadIdx.x < CSZ && e < E)
        atomicAdd(&g_histT[dst[e] * NCHP + blockIdx.x], 1);
}

// warp-per-node chunk scan + atomic row-base allocation (per-node edge order
// fixed -> output deterministic regardless of row placement).
__global__ void k_cscan(int N, int nchunk) {
    int w    = (blockIdx.x * blockDim.x + threadIdx.x) >> 5;
    int lane = threadIdx.x & 31;
    if (w >= N) return;
    int* row = g_histT + w * NCHP;
    int run = 0;
    for (int cb = 0; cb < nchunk; cb += 32) {
        int c = cb + lane;
        int v = (c < nchunk) ? row[c] : 0;
        int s = v;
        #pragma unroll
        for (int o = 1; o < 32; o <<= 1) {
            int t = __shfl_up_sync(0xffffffffu, s, o);
            if (lane >= o) s += t;
        }
        if (c < nchunk) row[c] = run + (s - v);
        run += __shfl_sync(0xffffffffu, s, 31);
    }
    if (lane == 0) {
        g_deg[w] = run;
        g_base[w] = atomicAdd(&g_ecnt, run);
    }
}

__global__ void k_scatter(const int* __restrict__ src, const int* __restrict__ dst,
                          int E) {
    __shared__ int sd[CSZ];
    int c = blockIdx.x, i = threadIdx.x;
    int e = c * CSZ + i;
    int d = -1, s = 0;
    if (e < E) { d = dst[e]; s = src[e]; }
    sd[i] = d;
    __syncthreads();
    if (d >= 0) {
        int rank = 0;
        for (int j = 0; j < i; ++j) rank += (sd[j] == d);
        g_csr[g_base[d] + g_histT[d * NCHP + c] + rank] = s;
    }
}

// --------------------- fp16 2-term HMMA GEMM + fused attn ------------------
constexpr int A_TILE_B = 9216;                  // 64 * 144
constexpr int B_TILE_B = 18432;                 // 128 * 144
constexpr int STAGE_B  = A_TILE_B + B_TILE_B;   // 27648
constexpr int SM_TOTAL = 3 * STAGE_B;           // 82944

__device__ __forceinline__ void load_chunk(uint32_t sb, int buf, int m0, int n0,
                                           int cc, int cpt, int tid, int layer) {
    int sp = cc / cpt;               // 0: A*Wh   1: A*Wl
    int ko = (cc - sp * cpt) * 64;
    const ushort* Ag = (const ushort*)g_A16 + (size_t)m0 * HD + ko;
    const ushort* Bg = (const ushort*)(sp == 1 ? g_Wl4 : g_Wh4)
                       + (size_t)layer * HD * HD + (size_t)n0 * HD + ko;
    uint32_t sa = sb + buf * STAGE_B;
    uint32_t sbb = sa + A_TILE_B;
    #pragma unroll
    for (int t = 0; t < 4; ++t) {
        int task = t * 128 + tid;
        int r = task >> 3, q = task & 7;
        cpa16(sa + r * 144 + q * 16, Ag + (size_t)r * HD + q * 8);
    }
    #pragma unroll
    for (int t = 0; t < 8; ++t) {
        int task = t * 128 + tid;
        int r = task >> 3, q = task & 7;
        cpa16(sbb + r * 144 + q * 16, Bg + (size_t)r * HD + q * 8);
    }
    cpa_commit();
}

__device__ __forceinline__ void ld_frags(uint32_t S, uint32_t a_off,
                                         uint32_t b_off, int ks,
                                         uint32_t a[2][4], uint32_t b[8][2]) {
    uint32_t kb = ks * 32;
    ldsm_x4(a[0][0], a[0][1], a[0][2], a[0][3], S + a_off + kb);
    ldsm_x4(a[1][0], a[1][1], a[1][2], a[1][3], S + a_off + 16 * 144 + kb);
    #pragma unroll
    for (int pr = 0; pr < 4; ++pr)
        ldsm_x4(b[pr * 2][0], b[pr * 2][1], b[pr * 2 + 1][0],
                b[pr * 2 + 1][1], S + b_off + pr * (16 * 144) + kb);
}

__global__ __launch_bounds__(128, 2) void k_mma(int M, int layer, int cpt,
                                                const float* __restrict__ al,
                                                const float* __restrict__ ar) {
    extern __shared__ char smem[];
    uint32_t sb = smem_u32(smem);
    int tid = threadIdx.x, lane = tid & 31, wid = tid >> 5;
    int warp_m = wid & 1, warp_n = wid >> 1;
    int g = lane >> 2, tig = lane & 3;
    int n0 = blockIdx.x * 128, m0 = blockIdx.y * 64;
    int nc = 2 * cpt;

    float acc[2][8][4];
    #pragma unroll
    for (int mt = 0; mt < 2; ++mt)
        #pragma unroll
        for (int nt = 0; nt < 8; ++nt)
            #pragma unroll
            for (int q = 0; q < 4; ++q) acc[mt][nt][q] = 0.f;

    load_chunk(sb, 0, m0, n0, 0, cpt, tid, layer);
    load_chunk(sb, 1, m0, n0, 1, cpt, tid, layer);

    uint32_t a_off = (uint32_t)((warp_m * 32 + (lane & 15)) * 144
                                + (lane >> 4) * 16);
    uint32_t b_off = (uint32_t)(A_TILE_B
                                + (warp_n * 64 + ((lane >> 4) & 1) * 8 + (lane & 7)) * 144
                                + ((lane >> 3) & 1) * 16);

    uint32_t a[2][2][4], b[2][8][2];
    for (int cc = 0; cc < nc; ++cc) {
        if (cc + 1 < nc) cpa_wait1(); else cpa_wait0();
        __syncthreads();
        if (cc + 2 < nc)
            load_chunk(sb, (cc + 2) % 3, m0, n0, cc + 2, cpt, tid, layer);
        uint32_t S = sb + (cc % 3) * STAGE_B;
        ld_frags(S, a_off, b_off, 0, a[0], b[0]);
        #pragma unroll
        for (int ks = 0; ks < 4; ++ks) {
            if (ks < 3)
                ld_frags(S, a_off, b_off, ks + 1, a[(ks + 1) & 1], b[(ks + 1) & 1]);
            #pragma unroll
            for (int mt = 0; mt < 2; ++mt)
                #pragma unroll
                for (int nt = 0; nt < 8; ++nt)
                    mma_f16(acc[mt][nt], a[ks & 1][mt], b[ks & 1][nt]);
        }
    }

    int h = (n0 >> 6) + warp_n;
    const float* alh = al + h * 64;
    const float* arh = ar + h * 64;
    #pragma unroll
    for (int mt = 0; mt < 2; ++mt) {
        int r0 = m0 + warp_m * 32 + mt * 16 + g;
        float el0 = 0.f, el1 = 0.f, er0 = 0.f, er1 = 0.f;
        #pragma unroll
        for (int nt = 0; nt < 8; ++nt) {
            int col = n0 + warp_n * 64 + nt * 8 + tig * 2;
            int d = nt * 8 + tig * 2;
            float av0 = __ldg(&alh[d]), av1 = __ldg(&alh[d + 1]);
            float rv0 = __ldg(&arh[d]), rv1 = __ldg(&arh[d + 1]);
            el0 = fmaf(acc[mt][nt][0], av0, fmaf(acc[mt][nt][1], av1, el0));
            el1 = fmaf(acc[mt][nt][2], av0, fmaf(acc[mt][nt][3], av1, el1));
            er0 = fmaf(acc[mt][nt][0], rv0, fmaf(acc[mt][nt][1], rv1, er0));
            er1 = fmaf(acc[mt][nt][2], rv0, fmaf(acc[mt][nt][3], rv1, er1));
            if (r0 < M)
                *(__half2*)(g_f16 + (size_t)r0 * HD + col) =
                    __floats2half2_rn(acc[mt][nt][0], acc[mt][nt][1]);
            if (r0 + 8 < M)
                *(__half2*)(g_f16 + (size_t)(r0 + 8) * HD + col) =
                    __floats2half2_rn(acc[mt][nt][2], acc[mt][nt][3]);
        }
        el0 += __shfl_xor_sync(0xffffffffu, el0, 1);
        el0 += __shfl_xor_sync(0xffffffffu, el0, 2);
        el1 += __shfl_xor_sync(0xffffffffu, el1, 1);
        el1 += __shfl_xor_sync(0xffffffffu, el1, 2);
        er0 += __shfl_xor_sync(0xffffffffu, er0, 1);
        er0 += __shfl_xor_sync(0xffffffffu, er0, 2);
        er1 += __shfl_xor_sync(0xffffffffu, er1, 1);
        er1 += __shfl_xor_sync(0xffffffffu, er1, 2);
        if (tig == 0) {
            if (r0 < M)     { g_el[r0 * NH + h] = el0;       g_er[r0 * NH + h] = er0; }
            if (r0 + 8 < M) { g_el[(r0 + 8) * NH + h] = el1; g_er[(r0 + 8) * NH + h] = er1; }
        }
    }
}

// ------ edge softmax + aggregation (warp/node, depth-1 pipeline, frozen) ----
template <bool FINAL>
__global__ void k_agg(const float* __restrict__ bias, const float* __restrict__ pw,
                      int N) {
    int w    = (blockIdx.x * blockDim.x + threadIdx.x) >> 5;
    int lane = threadIdx.x & 31;
    if (w >= N) return;
    float er_l = (lane < NH) ? g_er[w * NH + lane] : 0.f;
    int b0 = g_base[w], dg = g_deg[w];
    float4 a0 = {0.f, 0.f, 0.f, 0.f}, a1 = a0, a2 = a0;
    float den_l = 0.f;
    int h0 = lane >> 4;

    int sA = (dg > 0) ? __ldg(&g_csr[b0])     : 0;
    int sB = (dg > 1) ? __ldg(&g_csr[b0 + 1]) : 0;
    float elA = 0.f;
    uint2 u0A = {0, 0}, u1A = {0, 0}, u2A = {0, 0};
    if (dg > 0) {
        if (lane < NH) elA = __ldg(&g_el[sA * NH + lane]);
        const __half* fr = g_f16 + (size_t)sA * HD;
        u0A = *(const uint2*)(fr + lane * 4);
        u1A = *(const uint2*)(fr + 128 + lane * 4);
        u2A = *(const uint2*)(fr + 256 + lane * 4);
    }

    for (int p = 0; p < dg; ++p) {
        float el_cur = elA;
        uint2 u0 = u0A, u1 = u1A, u2 = u2A;
        int sN = sA = sB;
        if (p + 2 < dg) sB = __ldg(&g_csr[b0 + p + 2]);
        if (p + 1 < dg) {
            if (lane < NH) elA = __ldg(&g_el[sN * NH + lane]);
            const __half* fr = g_f16 + (size_t)sN * HD;
            u0A = *(const uint2*)(fr + lane * 4);
            u1A = *(const uint2*)(fr + 128 + lane * 4);
            u2A = *(const uint2*)(fr + 256 + lane * 4);
        }
        float w_l = 0.f;
        if (lane < NH) {
            float e = el_cur + er_l;
            e = e > 0.f ? e : 0.2f * e;
            w_l = __expf(e);
            den_l += w_l;
        }
        float w0 = __shfl_sync(0xffffffffu, w_l, h0);
        float w1 = __shfl_sync(0xffffffffu, w_l, h0 + 2);
        float w2 = __shfl_sync(0xffffffffu, w_l, h0 + 4);
        float2 p00 = __half22float2(*(const __half2*)&u0.x);
        float2 p01 = __half22float2(*(const __half2*)&u0.y);
        float2 p10 = __half22float2(*(const __half2*)&u1.x);
        float2 p11 = __half22float2(*(const __half2*)&u1.y);
        float2 p20 = __half22float2(*(const __half2*)&u2.x);
        float2 p21 = __half22float2(*(const __half2*)&u2.y);
        a0.x = fmaf(w0, p00.x, a0.x); a0.y = fmaf(w0, p00.y, a0.y);
        a0.z = fmaf(w0, p01.x, a0.z); a0.w = fmaf(w0, p01.y, a0.w);
        a1.x = fmaf(w1, p10.x, a1.x); a1.y = fmaf(w1, p10.y, a1.y);
        a1.z = fmaf(w1, p11.x, a1.z); a1.w = fmaf(w1, p11.y, a1.w);
        a2.x = fmaf(w2, p20.x, a2.x); a2.y = fmaf(w2, p20.y, a2.y);
        a2.z = fmaf(w2, p21.x, a2.z); a2.w = fmaf(w2, p21.y, a2.w);
    }

    float d0 = __shfl_sync(0xffffffffu, den_l, h0);
    float d1 = __shfl_sync(0xffffffffu, den_l, h0 + 2);
    float d2 = __shfl_sync(0xffffffffu, den_l, h0 + 4);
    float i0 = (dg > 0) ? 1.f / d0 : 0.f;
    float i1 = (dg > 0) ? 1.f / d1 : 0.f;
    float i2 = (dg > 0) ? 1.f / d2 : 0.f;
    const float4* b4 = reinterpret_cast<const float4*>(bias);
    float4 bv0 = b4[lane], bv1 = b4[lane + 32], bv2 = b4[lane + 64];
    float4 r0, r1, r2;
    r0.x = a0.x * i0 + bv0.x; r0.y = a0.y * i0 + bv0.y;
    r0.z = a0.z * i0 + bv0.z; r0.w = a0.w * i0 + bv0.w;
    r1.x = a1.x * i1 + bv1.x; r1.y = a1.y * i1 + bv1.y;
    r1.z = a1.z * i1 + bv1.z; r1.w = a1.w * i1 + bv1.w;
    r2.x = a2.x * i2 + bv2.x; r2.y = a2.y * i2 + bv2.y;
    r2.z = a2.z * i2 + bv2.z; r2.w = a2.w * i2 + bv2.w;

    if (!FINAL) {
        r0.x = r0.x > 0.f ? r0.x : expm1f(r0.x);
        r0.y = r0.y > 0.f ? r0.y : expm1f(r0.y);
        r0.z = r0.z > 0.f ? r0.z : expm1f(r0.z);
        r0.w = r0.w > 0.f ? r0.w : expm1f(r0.w);
        r1.x = r1.x > 0.f ? r1.x : expm1f(r1.x);
        r1.y = r1.y > 0.f ? r1.y : expm1f(r1.y);
        r1.z = r1.z > 0.f ? r1.z : expm1f(r1.z);
        r1.w = r1.w > 0.f ? r1.w : expm1f(r1.w);
        r2.x = r2.x > 0.f ? r2.x : expm1f(r2.x);
        r2.y = r2.y > 0.f ? r2.y : expm1f(r2.y);
        r2.z = r2.z > 0.f ? r2.z : expm1f(r2.z);
        r2.w = r2.w > 0.f ? r2.w : expm1f(r2.w);
        uint2* oA = reinterpret_cast<uint2*>(g_A16);
        size_t rb = (size_t)w * 96;
        uint2 v0 = {pack_h2(r0.x, r0.y), pack_h2(r0.z, r0.w)};
        uint2 v1 = {pack_h2(r1.x, r1.y), pack_h2(r1.z, r1.w)};
        uint2 v2 = {pack_h2(r2.x, r2.y), pack_h2(r2.z, r2.w)};
        oA[rb + lane]      = v0;
        oA[rb + lane + 32] = v1;
        oA[rb + lane + 64] = v2;
    } else {
        float pt0 = r0.x + r1.x + r2.x;
        float pt1 = r0.y + r1.y + r2.y;
        float pt2 = r0.z + r1.z + r2.z;
        float pt3 = r0.w + r1.w + r2.w;
        int dbase = (4 * lane) & 63;
        float c1 = pt0 * pw[dbase]     + pt1 * pw[dbase + 1]
                 + pt2 * pw[dbase + 2] + pt3 * pw[dbase + 3];
        float c2 = pt0 * pw[64 + dbase]     + pt1 * pw[64 + dbase + 1]
                 + pt2 * pw[64 + dbase + 2] + pt3 * pw[64 + dbase + 3];
        #pragma unroll
        for (int o = 16; o; o >>= 1) {
            c1 += __shfl_xor_sync(0xffffffffu, c1, o);
            c2 += __shfl_xor_sync(0xffffffffu, c2, o);
        }
        if (lane == 0) {
            g_s1[w] = c1 * (1.f / 6.f);
            g_s2[w] = c2 * (1.f / 6.f);
        }
    }
}

// --------------------------- pairwise output -------------------------------
__device__ __forceinline__ float tanhfast(float x) {
    float xc = fminf(fmaxf(x, -15.f), 15.f);
    float t = __expf(2.f * xc);
    return __fdividef(t - 1.f, t + 1.f);
}

__global__ void k_pair(const float* __restrict__ dis, const float* __restrict__ pw,
                       const float* __restrict__ pb, float* __restrict__ out, int N) {
    int t  = blockIdx.x * blockDim.x + threadIdx.x;
    int i  = blockIdx.y;
    int nq = N >> 2;
    int j4 = t * 2;
    if (j4 >= nq) return;
    float c    = __ldg(&pw[128]);
    float base = g_s2[i] + __ldg(pb);
    const float4* dp = reinterpret_cast<const float4*>(dis) + (size_t)i * nq;
    const float4* sp = reinterpret_cast<const float4*>(g_s1);
    float4*       op = reinterpret_cast<float4*>(out) + (size_t)i * nq;
    float4 d0 = dp[j4], d1 = dp[j4 + 1];
    float4 s0 = sp[j4], s1 = sp[j4 + 1];
    float4 r0, r1;
    r0.x = tanhfast(base + s0.x + d0.x * c);
    r0.y = tanhfast(base + s0.y + d0.y * c);
    r0.z = tanhfast(base + s0.z + d0.z * c);
    r0.w = tanhfast(base + s0.w + d0.w * c);
    r1.x = tanhfast(base + s1.x + d1.x * c);
    r1.y = tanhfast(base + s1.y + d1.y * c);
    r1.z = tanhfast(base + s1.z + d1.z * c);
    r1.w = tanhfast(base + s1.w + d1.w * c);
    op[j4]     = r0;
    op[j4 + 1] = r1;
}

// ------------------------------- launcher -----------------------------------
extern "C" void kernel_launch(void* const* d_in, const int* in_sizes, int n_in,
                              void* d_out, int out_size) {
    const float* nfeats = (const float*)d_in[0];
    const float* dis    = (const float*)d_in[1];
    const int*   src    = (const int*)d_in[2];
    const int*   dst    = (const int*)d_in[3];
    const float* pw     = (const float*)d_in[20];
    const float* pb     = (const float*)d_in[21];

    const int IN = 131;
    int N = in_sizes[0] / IN;             // 5000
    int E = in_sizes[2];                  // 160000
    int nchunk = (E + CSZ - 1) / CSZ;
    int Mpad = ((N + 127) / 128) * 128;   // 5120

    cudaFuncSetAttribute(k_mma, cudaFuncAttributeMaxDynamicSharedMemorySize,
                         SM_TOTAL);

    dim3 gg(HD / 128, Mpad / 64);         // (3, 80) = 240 CTAs
    int nwb = (N * 32 + 255) / 256;

    // Fork a second stream for the CSR chain (capture-safe event fork).
    // Streams/events are intentionally not destroyed: destroying a forked
    // stream during capture would invalidate the graph; a handful of host
    // objects leak per capture call, no device memory involved.
    cudaStream_t s2;
    cudaStreamCreate(&s2);
    cudaEvent_t eF, eJ;
    cudaEventCreateWithFlags(&eF, cudaEventDisableTiming);
    cudaEventCreateWithFlags(&eJ, cudaEventDisableTiming);

    cudaEventRecord(eF, 0);
    cudaStreamWaitEvent(s2, eF, 0);

    // stream 0: conversions -> layer-0 GEMM
    int conv_elems = Mpad * HD + 4 * HD * HD;
    k_convAB<<<(conv_elems + 255) / 256, 256>>>(
        nfeats, (const float*)d_in[4], (const float*)d_in[8],
        (const float*)d_in[12], (const float*)d_in[16], N, Mpad);

    // stream 2: CSR build (zero -> hist -> cscan -> scatter), overlaps conv+mma0
    k_zero<<<(NMAXI * NCHP / 4 + 255) / 256, 256, 0, s2>>>();
    k_hist<<<nchunk, CSZ, 0, s2>>>(dst, E);

    k_mma<<<gg, 128, SM_TOTAL>>>(N, 0, 3,
        (const float*)d_in[5], (const float*)d_in[6]);   // launch idx 3

    k_cscan<<<(N * 32 + 255) / 256, 256, 0, s2>>>(N, nchunk);
    k_scatter<<<nchunk, CSZ, 0, s2>>>(src, dst, E);
    cudaEventRecord(eJ, s2);
    cudaStreamWaitEvent(0, eJ, 0);        // join before first aggregation

    for (int l = 0; l < 4; ++l) {
        const float* b = (const float*)d_in[7 + 4 * l];
        if (l > 0) {
            const float* al = (const float*)d_in[5 + 4 * l];
            const float* ar = (const float*)d_in[6 + 4 * l];
            k_mma<<<gg, 128, SM_TOTAL>>>(N, l, 6, al, ar);
        }
        if (l < 3) k_agg<false><<<nwb, 256>>>(b, nullptr, N);
        else       k_agg<true><<<nwb, 256>>>(b, pw, N);
    }

    int nq = N / 4;
    dim3 gp((nq / 2 + 255) / 256, N);
    k_pair<<<gp, 256>>>(dis, pw, pb, (float*)d_out, N);
}

// round 17
// speedup vs baseline: 1.1509x; 1.0262x over previous
#include <cuda_runtime.h>
#include <cuda_bf16.h>
#include <cuda_fp16.h>
#include <cstdint>

// ---------------------------------------------------------------------------
// GAT (4 layers) + pairwise tanh for GB300 (sm_103a harness, compute_103 PTX).
// GEMM: fp16 HMMA, A single fp16, W fp16 hi/lo split (C = A*Wh + A*Wl),
// single-A-pass K loop: each chunk loads {A, Wh, Wl} once and issues both
// terms' MMAs (half the syncs, half the A traffic). 2-stage cp.async pipeline,
// ldmatrix.x4 fragments, fused attention-dot epilogue, fp16 f.
// Aggregation: 1 warp/node, depth-1 pipeline (frozen). CSR on forked stream.
// ---------------------------------------------------------------------------

constexpr int HD  = 384;        // H*D
constexpr int NH  = 6;          // heads
constexpr int NMAXI = 5120;     // max nodes (actual 5000), mult of 128
constexpr int EMAXI = 163840;
constexpr int CSZ   = 320;      // edges per sort chunk
constexpr int NCHP  = 512;      // chunk stride (chunks actual 500)

// ------------------------- device scratch ----------------------------------
__device__ __align__(16) __half g_f16[NMAXI * HD];           // fp16 GEMM out
__device__ __align__(16) __half g_A16[NMAXI * HD];           // fp16 layer input
__device__ __align__(16) __half g_Wh4[4 * HD * HD];          // W^T hi [l][n][k]
__device__ __align__(16) __half g_Wl4[4 * HD * HD];          // W^T lo
__device__ float g_el[NMAXI * NH];
__device__ float g_er[NMAXI * NH];
__device__ __align__(16) int g_histT[NMAXI * NCHP];          // node-major counts
__device__ int   g_base[NMAXI];
__device__ int   g_deg[NMAXI];
__device__ int   g_csr[EMAXI];
__device__ int   g_ecnt;                                     // edge allocator
__device__ __align__(16) float g_s1[NMAXI];
__device__ __align__(16) float g_s2[NMAXI];

// --------------------------- helpers ----------------------------------------
__device__ __forceinline__ uint32_t smem_u32(const void* p) {
    uint32_t a;
    asm("{ .reg .u64 t; cvta.to.shared.u64 t, %1; cvt.u32.u64 %0, t; }"
        : "=r"(a) : "l"(p));
    return a;
}
__device__ __forceinline__ void cpa16(uint32_t s, const void* g) {
    asm volatile("cp.async.ca.shared.global [%0], [%1], 16;"
                 :: "r"(s), "l"(g) : "memory");
}
__device__ __forceinline__ void cpa_commit() {
    asm volatile("cp.async.commit_group;" ::: "memory");
}
__device__ __forceinline__ void cpa_wait0() {
    asm volatile("cp.async.wait_group 0;" ::: "memory");
}
__device__ __forceinline__ void cpa_wait1() {
    asm volatile("cp.async.wait_group 1;" ::: "memory");
}
__device__ __forceinline__ void mma_f16(float* d, const uint32_t* a,
                                        const uint32_t* b) {
    asm volatile(
        "mma.sync.aligned.m16n8k16.row.col.f32.f16.f16.f32 "
        "{%0,%1,%2,%3}, {%4,%5,%6,%7}, {%8,%9}, {%0,%1,%2,%3};"
        : "+f"(d[0]), "+f"(d[1]), "+f"(d[2]), "+f"(d[3])
        : "r"(a[0]), "r"(a[1]), "r"(a[2]), "r"(a[3]), "r"(b[0]), "r"(b[1]));
}
__device__ __forceinline__ void ldsm_x4(uint32_t& r0, uint32_t& r1,
                                        uint32_t& r2, uint32_t& r3,
                                        uint32_t addr) {
    asm volatile("ldmatrix.sync.aligned.m8n8.x4.shared.b16 {%0,%1,%2,%3}, [%4];"
                 : "=r"(r0), "=r"(r1), "=r"(r2), "=r"(r3) : "r"(addr));
}
__device__ __forceinline__ uint32_t pack_h2(float a, float b) {
    __half2 h = __floats2half2_rn(a, b);
    return *reinterpret_cast<uint32_t*>(&h);
}

// ---------------- conversions (A fp16 + W hi/lo splits) ---------------------
__global__ void k_convAB(const float* __restrict__ nfeats,
                         const float* __restrict__ w0, const float* __restrict__ w1,
                         const float* __restrict__ w2, const float* __restrict__ w3,
                         int M, int Mpad) {
    int idx = blockIdx.x * blockDim.x + threadIdx.x;
    int asz = Mpad * HD;
    int bsz = 4 * HD * HD;
    if (idx < asz) {
        int m = idx / HD, k = idx - m * HD;
        float v = (m < M && k < 131) ? nfeats[(size_t)m * 131 + k] : 0.f;
        g_A16[idx] = __float2half_rn(v);
    } else if (idx < asz + bsz) {
        int r = idx - asz;
        int lb = r / (HD * HD);
        int q = r - lb * HD * HD;
        int k = q / HD, n = q - k * HD;
        const float* W = (lb == 0) ? w0 : (lb == 1) ? w1 : (lb == 2) ? w2 : w3;
        float v = (lb == 0 && k >= 131) ? 0.f : W[(size_t)k * HD + n];
        __half h = __float2half_rn(v);
        __half l = __float2half_rn(v - __half2float(h));
        g_Wh4[(size_t)lb * HD * HD + (size_t)n * HD + k] = h;
        g_Wl4[(size_t)lb * HD * HD + (size_t)n * HD + k] = l;
    }
}

// ----------------------------- CSR build (stream 2) -------------------------
__global__ void k_zero() {
    int i = blockIdx.x * blockDim.x + threadIdx.x;
    if (i == 0) g_ecnt = 0;
    if (i < NMAXI * NCHP / 4)
        reinterpret_cast<int4*>(g_histT)[i] = make_int4(0, 0, 0, 0);
}

__global__ void k_hist(const int* __restrict__ dst, int E) {
    int e = blockIdx.x * CSZ + threadIdx.x;
    if (threadIdx.x < CSZ && e < E)
        atomicAdd(&g_histT[dst[e] * NCHP + blockIdx.x], 1);
}

__global__ void k_cscan(int N, int nchunk) {
    int w    = (blockIdx.x * blockDim.x + threadIdx.x) >> 5;
    int lane = threadIdx.x & 31;
    if (w >= N) return;
    int* row = g_histT + w * NCHP;
    int run = 0;
    for (int cb = 0; cb < nchunk; cb += 32) {
        int c = cb + lane;
        int v = (c < nchunk) ? row[c] : 0;
        int s = v;
        #pragma unroll
        for (int o = 1; o < 32; o <<= 1) {
            int t = __shfl_up_sync(0xffffffffu, s, o);
            if (lane >= o) s += t;
        }
        if (c < nchunk) row[c] = run + (s - v);
        run += __shfl_sync(0xffffffffu, s, 31);
    }
    if (lane == 0) {
        g_deg[w] = run;
        g_base[w] = atomicAdd(&g_ecnt, run);
    }
}

__global__ void k_scatter(const int* __restrict__ src, const int* __restrict__ dst,
                          int E) {
    __shared__ int sd[CSZ];
    int c = blockIdx.x, i = threadIdx.x;
    int e = c * CSZ + i;
    int d = -1, s = 0;
    if (e < E) { d = dst[e]; s = src[e]; }
    sd[i] = d;
    __syncthreads();
    if (d >= 0) {
        int rank = 0;
        for (int j = 0; j < i; ++j) rank += (sd[j] == d);
        g_csr[g_base[d] + g_histT[d * NCHP + c] + rank] = s;
    }
}

// --------- fp16 2-term HMMA GEMM, single-A-pass chunks + fused attn --------
// block 64x128, 128 thr, 4 warps 32x64. Chunk = {A 64x64, Wh 128x64,
// Wl 128x64}; both terms' MMAs per chunk. 2-stage cp.async pipeline.
constexpr int A_TILE_B  = 9216;                  // 64 * 144
constexpr int B_TILE_B  = 18432;                 // 128 * 144
constexpr int STAGE_B   = A_TILE_B + 2 * B_TILE_B;   // 46080
constexpr int SM_TOTAL  = 2 * STAGE_B;               // 92160

__device__ __forceinline__ void load_chunk(uint32_t sb, int buf, int m0, int n0,
                                           int cc, int tid, int layer) {
    int ko = cc * 64;
    const ushort* Ag  = (const ushort*)g_A16 + (size_t)m0 * HD + ko;
    const ushort* Bhg = (const ushort*)g_Wh4 + (size_t)layer * HD * HD
                        + (size_t)n0 * HD + ko;
    const ushort* Blg = (const ushort*)g_Wl4 + (size_t)layer * HD * HD
                        + (size_t)n0 * HD + ko;
    uint32_t sa  = sb + buf * STAGE_B;
    uint32_t sbh = sa + A_TILE_B;
    uint32_t sbl = sbh + B_TILE_B;
    #pragma unroll
    for (int t = 0; t < 4; ++t) {           // A: 64 rows x 8 q
        int task = t * 128 + tid;
        int r = task >> 3, q = task & 7;
        cpa16(sa + r * 144 + q * 16, Ag + (size_t)r * HD + q * 8);
    }
    #pragma unroll
    for (int t = 0; t < 8; ++t) {           // Wh: 128 rows x 8 q
        int task = t * 128 + tid;
        int r = task >> 3, q = task & 7;
        cpa16(sbh + r * 144 + q * 16, Bhg + (size_t)r * HD + q * 8);
    }
    #pragma unroll
    for (int t = 0; t < 8; ++t) {           // Wl: 128 rows x 8 q
        int task = t * 128 + tid;
        int r = task >> 3, q = task & 7;
        cpa16(sbl + r * 144 + q * 16, Blg + (size_t)r * HD + q * 8);
    }
    cpa_commit();
}

__global__ __launch_bounds__(128, 2) void k_mma(int M, int layer, int nc,
                                                const float* __restrict__ al,
                                                const float* __restrict__ ar) {
    extern __shared__ char smem[];
    uint32_t sb = smem_u32(smem);
    int tid = threadIdx.x, lane = tid & 31, wid = tid >> 5;
    int warp_m = wid & 1, warp_n = wid >> 1;
    int g = lane >> 2, tig = lane & 3;
    int n0 = blockIdx.x * 128, m0 = blockIdx.y * 64;

    float acc[2][8][4];
    #pragma unroll
    for (int mt = 0; mt < 2; ++mt)
        #pragma unroll
        for (int nt = 0; nt < 8; ++nt)
            #pragma unroll
            for (int q = 0; q < 4; ++q) acc[mt][nt][q] = 0.f;

    load_chunk(sb, 0, m0, n0, 0, tid, layer);

    uint32_t a_off = (uint32_t)((warp_m * 32 + (lane & 15)) * 144
                                + (lane >> 4) * 16);
    uint32_t b_off = (uint32_t)(A_TILE_B
                                + (warp_n * 64 + ((lane >> 4) & 1) * 8 + (lane & 7)) * 144
                                + ((lane >> 3) & 1) * 16);

    for (int cc = 0; cc < nc; ++cc) {
        if (cc + 1 < nc) {
            load_chunk(sb, (cc + 1) & 1, m0, n0, cc + 1, tid, layer);
            cpa_wait1();                   // chunk cc complete, cc+1 in flight
        } else {
            cpa_wait0();
        }
        __syncthreads();
        uint32_t S = sb + (cc & 1) * STAGE_B;
        #pragma unroll
        for (int ks = 0; ks < 4; ++ks) {
            uint32_t kb = ks * 32;
            uint32_t a[2][4], bh[8][2], bl[8][2];
            ldsm_x4(a[0][0], a[0][1], a[0][2], a[0][3], S + a_off + kb);
            ldsm_x4(a[1][0], a[1][1], a[1][2], a[1][3],
                    S + a_off + 16 * 144 + kb);
            #pragma unroll
            for (int pr = 0; pr < 4; ++pr)
                ldsm_x4(bh[pr * 2][0], bh[pr * 2][1], bh[pr * 2 + 1][0],
                        bh[pr * 2 + 1][1], S + b_off + pr * (16 * 144) + kb);
            #pragma unroll
            for (int pr = 0; pr < 4; ++pr)
                ldsm_x4(bl[pr * 2][0], bl[pr * 2][1], bl[pr * 2 + 1][0],
                        bl[pr * 2 + 1][1],
                        S + b_off + B_TILE_B + pr * (16 * 144) + kb);
            #pragma unroll
            for (int mt = 0; mt < 2; ++mt)
                #pragma unroll
                for (int nt = 0; nt < 8; ++nt)
                    mma_f16(acc[mt][nt], a[mt], bh[nt]);
            #pragma unroll
            for (int mt = 0; mt < 2; ++mt)
                #pragma unroll
                for (int nt = 0; nt < 8; ++nt)
                    mma_f16(acc[mt][nt], a[mt], bl[nt]);
        }
        __syncthreads();
    }

    // ---- epilogue: write fp16 f + fused attention dots (fp32 exact) ----
    int h = (n0 >> 6) + warp_n;
    const float* alh = al + h * 64;
    const float* arh = ar + h * 64;
    #pragma unroll
    for (int mt = 0; mt < 2; ++mt) {
        int r0 = m0 + warp_m * 32 + mt * 16 + g;
        float el0 = 0.f, el1 = 0.f, er0 = 0.f, er1 = 0.f;
        #pragma unroll
        for (int nt = 0; nt < 8; ++nt) {
            int col = n0 + warp_n * 64 + nt * 8 + tig * 2;
            int d = nt * 8 + tig * 2;
            float av0 = __ldg(&alh[d]), av1 = __ldg(&alh[d + 1]);
            float rv0 = __ldg(&arh[d]), rv1 = __ldg(&arh[d + 1]);
            el0 = fmaf(acc[mt][nt][0], av0, fmaf(acc[mt][nt][1], av1, el0));
            el1 = fmaf(acc[mt][nt][2], av0, fmaf(acc[mt][nt][3], av1, el1));
            er0 = fmaf(acc[mt][nt][0], rv0, fmaf(acc[mt][nt][1], rv1, er0));
            er1 = fmaf(acc[mt][nt][2], rv0, fmaf(acc[mt][nt][3], rv1, er1));
            if (r0 < M)
                *(__half2*)(g_f16 + (size_t)r0 * HD + col) =
                    __floats2half2_rn(acc[mt][nt][0], acc[mt][nt][1]);
            if (r0 + 8 < M)
                *(__half2*)(g_f16 + (size_t)(r0 + 8) * HD + col) =
                    __floats2half2_rn(acc[mt][nt][2], acc[mt][nt][3]);
        }
        el0 += __shfl_xor_sync(0xffffffffu, el0, 1);
        el0 += __shfl_xor_sync(0xffffffffu, el0, 2);
        el1 += __shfl_xor_sync(0xffffffffu, el1, 1);
        el1 += __shfl_xor_sync(0xffffffffu, el1, 2);
        er0 += __shfl_xor_sync(0xffffffffu, er0, 1);
        er0 += __shfl_xor_sync(0xffffffffu, er0, 2);
        er1 += __shfl_xor_sync(0xffffffffu, er1, 1);
        er1 += __shfl_xor_sync(0xffffffffu, er1, 2);
        if (tig == 0) {
            if (r0 < M)     { g_el[r0 * NH + h] = el0;       g_er[r0 * NH + h] = er0; }
            if (r0 + 8 < M) { g_el[(r0 + 8) * NH + h] = el1; g_er[(r0 + 8) * NH + h] = er1; }
        }
    }
}

// ------ edge softmax + aggregation (warp/node, depth-1 pipeline, frozen) ----
template <bool FINAL>
__global__ void k_agg(const float* __restrict__ bias, const float* __restrict__ pw,
                      int N) {
    int w    = (blockIdx.x * blockDim.x + threadIdx.x) >> 5;
    int lane = threadIdx.x & 31;
    if (w >= N) return;
    float er_l = (lane < NH) ? g_er[w * NH + lane] : 0.f;
    int b0 = g_base[w], dg = g_deg[w];
    float4 a0 = {0.f, 0.f, 0.f, 0.f}, a1 = a0, a2 = a0;
    float den_l = 0.f;
    int h0 = lane >> 4;

    int sA = (dg > 0) ? __ldg(&g_csr[b0])     : 0;
    int sB = (dg > 1) ? __ldg(&g_csr[b0 + 1]) : 0;
    float elA = 0.f;
    uint2 u0A = {0, 0}, u1A = {0, 0}, u2A = {0, 0};
    if (dg > 0) {
        if (lane < NH) elA = __ldg(&g_el[sA * NH + lane]);
        const __half* fr = g_f16 + (size_t)sA * HD;
        u0A = *(const uint2*)(fr + lane * 4);
        u1A = *(const uint2*)(fr + 128 + lane * 4);
        u2A = *(const uint2*)(fr + 256 + lane * 4);
    }

    for (int p = 0; p < dg; ++p) {
        float el_cur = elA;
        uint2 u0 = u0A, u1 = u1A, u2 = u2A;
        int sN = sA = sB;
        if (p + 2 < dg) sB = __ldg(&g_csr[b0 + p + 2]);
        if (p + 1 < dg) {
            if (lane < NH) elA = __ldg(&g_el[sN * NH + lane]);
            const __half* fr = g_f16 + (size_t)sN * HD;
            u0A = *(const uint2*)(fr + lane * 4);
            u1A = *(const uint2*)(fr + 128 + lane * 4);
            u2A = *(const uint2*)(fr + 256 + lane * 4);
        }
        float w_l = 0.f;
        if (lane < NH) {
            float e = el_cur + er_l;
            e = e > 0.f ? e : 0.2f * e;
            w_l = __expf(e);
            den_l += w_l;
        }
        float w0 = __shfl_sync(0xffffffffu, w_l, h0);
        float w1 = __shfl_sync(0xffffffffu, w_l, h0 + 2);
        float w2 = __shfl_sync(0xffffffffu, w_l, h0 + 4);
        float2 p00 = __half22float2(*(const __half2*)&u0.x);
        float2 p01 = __half22float2(*(const __half2*)&u0.y);
        float2 p10 = __half22float2(*(const __half2*)&u1.x);
        float2 p11 = __half22float2(*(const __half2*)&u1.y);
        float2 p20 = __half22float2(*(const __half2*)&u2.x);
        float2 p21 = __half22float2(*(const __half2*)&u2.y);
        a0.x = fmaf(w0, p00.x, a0.x); a0.y = fmaf(w0, p00.y, a0.y);
        a0.z = fmaf(w0, p01.x, a0.z); a0.w = fmaf(w0, p01.y, a0.w);
        a1.x = fmaf(w1, p10.x, a1.x); a1.y = fmaf(w1, p10.y, a1.y);
        a1.z = fmaf(w1, p11.x, a1.z); a1.w = fmaf(w1, p11.y, a1.w);
        a2.x = fmaf(w2, p20.x, a2.x); a2.y = fmaf(w2, p20.y, a2.y);
        a2.z = fmaf(w2, p21.x, a2.z); a2.w = fmaf(w2, p21.y, a2.w);
    }

    float d0 = __shfl_sync(0xffffffffu, den_l, h0);
    float d1 = __shfl_sync(0xffffffffu, den_l, h0 + 2);
    float d2 = __shfl_sync(0xffffffffu, den_l, h0 + 4);
    float i0 = (dg > 0) ? 1.f / d0 : 0.f;
    float i1 = (dg > 0) ? 1.f / d1 : 0.f;
    float i2 = (dg > 0) ? 1.f / d2 : 0.f;
    const float4* b4 = reinterpret_cast<const float4*>(bias);
    float4 bv0 = b4[lane], bv1 = b4[lane + 32], bv2 = b4[lane + 64];
    float4 r0, r1, r2;
    r0.x = a0.x * i0 + bv0.x; r0.y = a0.y * i0 + bv0.y;
    r0.z = a0.z * i0 + bv0.z; r0.w = a0.w * i0 + bv0.w;
    r1.x = a1.x * i1 + bv1.x; r1.y = a1.y * i1 + bv1.y;
    r1.z = a1.z * i1 + bv1.z; r1.w = a1.w * i1 + bv1.w;
    r2.x = a2.x * i2 + bv2.x; r2.y = a2.y * i2 + bv2.y;
    r2.z = a2.z * i2 + bv2.z; r2.w = a2.w * i2 + bv2.w;

    if (!FINAL) {
        r0.x = r0.x > 0.f ? r0.x : expm1f(r0.x);
        r0.y = r0.y > 0.f ? r0.y : expm1f(r0.y);
        r0.z = r0.z > 0.f ? r0.z : expm1f(r0.z);
        r0.w = r0.w > 0.f ? r0.w : expm1f(r0.w);
        r1.x = r1.x > 0.f ? r1.x : expm1f(r1.x);
        r1.y = r1.y > 0.f ? r1.y : expm1f(r1.y);
        r1.z = r1.z > 0.f ? r1.z : expm1f(r1.z);
        r1.w = r1.w > 0.f ? r1.w : expm1f(r1.w);
        r2.x = r2.x > 0.f ? r2.x : expm1f(r2.x);
        r2.y = r2.y > 0.f ? r2.y : expm1f(r2.y);
        r2.z = r2.z > 0.f ? r2.z : expm1f(r2.z);
        r2.w = r2.w > 0.f ? r2.w : expm1f(r2.w);
        uint2* oA = reinterpret_cast<uint2*>(g_A16);
        size_t rb = (size_t)w * 96;
        uint2 v0 = {pack_h2(r0.x, r0.y), pack_h2(r0.z, r0.w)};
        uint2 v1 = {pack_h2(r1.x, r1.y), pack_h2(r1.z, r1.w)};
        uint2 v2 = {pack_h2(r2.x, r2.y), pack_h2(r2.z, r2.w)};
        oA[rb + lane]      = v0;
        oA[rb + lane + 32] = v1;
        oA[rb + lane + 64] = v2;
    } else {
        float pt0 = r0.x + r1.x + r2.x;
        float pt1 = r0.y + r1.y + r2.y;
        float pt2 = r0.z + r1.z + r2.z;
        float pt3 = r0.w + r1.w + r2.w;
        int dbase = (4 * lane) & 63;
        float c1 = pt0 * pw[dbase]     + pt1 * pw[dbase + 1]
                 + pt2 * pw[dbase + 2] + pt3 * pw[dbase + 3];
        float c2 = pt0 * pw[64 + dbase]     + pt1 * pw[64 + dbase + 1]
                 + pt2 * pw[64 + dbase + 2] + pt3 * pw[64 + dbase + 3];
        #pragma unroll
        for (int o = 16; o; o >>= 1) {
            c1 += __shfl_xor_sync(0xffffffffu, c1, o);
            c2 += __shfl_xor_sync(0xffffffffu, c2, o);
        }
        if (lane == 0) {
            g_s1[w] = c1 * (1.f / 6.f);
            g_s2[w] = c2 * (1.f / 6.f);
        }
    }
}

// --------------------------- pairwise output -------------------------------
__device__ __forceinline__ float tanhfast(float x) {
    float xc = fminf(fmaxf(x, -15.f), 15.f);
    float t = __expf(2.f * xc);
    return __fdividef(t - 1.f, t + 1.f);
}

__global__ void k_pair(const float* __restrict__ dis, const float* __restrict__ pw,
                       const float* __restrict__ pb, float* __restrict__ out, int N) {
    int t  = blockIdx.x * blockDim.x + threadIdx.x;
    int i  = blockIdx.y;
    int nq = N >> 2;
    int j4 = t * 2;
    if (j4 >= nq) return;
    float c    = __ldg(&pw[128]);
    float base = g_s2[i] + __ldg(pb);
    const float4* dp = reinterpret_cast<const float4*>(dis) + (size_t)i * nq;
    const float4* sp = reinterpret_cast<const float4*>(g_s1);
    float4*       op = reinterpret_cast<float4*>(out) + (size_t)i * nq;
    float4 d0 = dp[j4], d1 = dp[j4 + 1];
    float4 s0 = sp[j4], s1 = sp[j4 + 1];
    float4 r0, r1;
    r0.x = tanhfast(base + s0.x + d0.x * c);
    r0.y = tanhfast(base + s0.y + d0.y * c);
    r0.z = tanhfast(base + s0.z + d0.z * c);
    r0.w = tanhfast(base + s0.w + d0.w * c);
    r1.x = tanhfast(base + s1.x + d1.x * c);
    r1.y = tanhfast(base + s1.y + d1.y * c);
    r1.z = tanhfast(base + s1.z + d1.z * c);
    r1.w = tanhfast(base + s1.w + d1.w * c);
    op[j4]     = r0;
    op[j4 + 1] = r1;
}

// ------------------------------- launcher -----------------------------------
extern "C" void kernel_launch(void* const* d_in, const int* in_sizes, int n_in,
                              void* d_out, int out_size) {
    const float* nfeats = (const float*)d_in[0];
    const float* dis    = (const float*)d_in[1];
    const int*   src    = (const int*)d_in[2];
    const int*   dst    = (const int*)d_in[3];
    const float* pw     = (const float*)d_in[20];
    const float* pb     = (const float*)d_in[21];

    const int IN = 131;
    int N = in_sizes[0] / IN;             // 5000
    int E = in_sizes[2];                  // 160000
    int nchunk = (E + CSZ - 1) / CSZ;
    int Mpad = ((N + 127) / 128) * 128;   // 5120

    cudaFuncSetAttribute(k_mma, cudaFuncAttributeMaxDynamicSharedMemorySize,
                         SM_TOTAL);

    dim3 gg(HD / 128, Mpad / 64);         // (3, 80) = 240 CTAs
    int nwb = (N * 32 + 255) / 256;

    // Fork a second stream for the CSR chain (capture-safe event fork).
    cudaStream_t s2;
    cudaStreamCreate(&s2);
    cudaEvent_t eF, eJ;
    cudaEventCreateWithFlags(&eF, cudaEventDisableTiming);
    cudaEventCreateWithFlags(&eJ, cudaEventDisableTiming);

    cudaEventRecord(eF, 0);
    cudaStreamWaitEvent(s2, eF, 0);

    // stream 0: conversions -> layer-0 GEMM
    int conv_elems = Mpad * HD + 4 * HD * HD;
    k_convAB<<<(conv_elems + 255) / 256, 256>>>(
        nfeats, (const float*)d_in[4], (const float*)d_in[8],
        (const float*)d_in[12], (const float*)d_in[16], N, Mpad);

    // stream 2: CSR build (zero -> hist -> cscan -> scatter)
    k_zero<<<(NMAXI * NCHP / 4 + 255) / 256, 256, 0, s2>>>();
    k_hist<<<nchunk, CSZ, 0, s2>>>(dst, E);

    k_mma<<<gg, 128, SM_TOTAL>>>(N, 0, 3,
        (const float*)d_in[5], (const float*)d_in[6]);   // launch idx 3

    k_cscan<<<(N * 32 + 255) / 256, 256, 0, s2>>>(N, nchunk);
    k_scatter<<<nchunk, CSZ, 0, s2>>>(src, dst, E);
    cudaEventRecord(eJ, s2);
    cudaStreamWaitEvent(0, eJ, 0);        // join before first aggregation

    for (int l = 0; l < 4; ++l) {
        const float* b = (const float*)d_in[7 + 4 * l];
        if (l > 0) {
            const float* al = (const float*)d_in[5 + 4 * l];
            const float* ar = (const float*)d_in[6 + 4 * l];
            k_mma<<<gg, 128, SM_TOTAL>>>(N, l, 6, al, ar);
        }
        if (l < 3) k_agg<false><<<nwb, 256>>>(b, nullptr, N);
        else       k_agg<true><<<nwb, 256>>>(b, pw, N);
    }

    int nq = N / 4;
    dim3 gp((nq / 2 + 255) / 256, N);
    k_pair<<<gp, 256>>>(dis, pw, pb, (float*)d_out, N);
}